// round 3
// baseline (speedup 1.0000x reference)
#include <cuda_runtime.h>
#include <math.h>
#include <float.h>

// ---------------- problem constants (fixed by setup_inputs) ----------------
#define DFULL 60801          // 3 * (15200+3800+950+247+70) anchors per image
#define DSEL  3951           // 1000+1000+1000+741+210 selected per image
#define NTOT  7902           // 2 images * DSEL
#define LOG_MAXF 4.135166556742356f

__device__ const int d_HW[5]   = {15200, 3800, 950, 247, 70};
__device__ const int d_K[5]    = {1000, 1000, 1000, 741, 210};
__device__ const int d_AOFF[5] = {0, 45600, 57000, 59850, 60591};
__device__ const int d_COFF[5] = {0, 1000, 2000, 3000, 3741};

// ---------------- scratch (static device memory; no allocs) ----------------
__device__ float    g_h[10376704];        // conv+relu outputs, per-level NCHW
__device__ float    g_logit[2 * DFULL];
__device__ float    g_reg[2 * DFULL * 4];
__device__ int      g_topidx[10 * 1000];
__device__ float    g_toplog[10 * 1000];
__device__ float4   g_cbox[NTOT];
__device__ float    g_cscore[NTOT];
__device__ int      g_cvalid[NTOT];
__device__ float    g_csc[NTOT];
__device__ unsigned g_maxbits;            // global max box coord (fp32 bits)

// ---------------- conv 3x3 (SAME) + bias + relu ----------------
__global__ void conv_kernel(const float* __restrict__ x,
                            const float* __restrict__ cw,
                            const float* __restrict__ cb,
                            int H, int W, int hoff) {
    __shared__ float ins[16 * 10 * 18];   // 16 ic x (8+2) x (16+2)
    __shared__ float wsm[16 * 9 * 64];    // 16 ic x 9 taps x 64 oc

    const int tid = threadIdx.x;
    const int x0 = blockIdx.x * 16, y0 = blockIdx.y * 8;
    const int img = blockIdx.z >> 2;
    const int ocBase = (blockIdx.z & 3) * 64;
    const int lane_px = tid & 31;
    const int ocg = tid >> 5;
    const int HWp = H * W;

    int pr[4], pc[4];
#pragma unroll
    for (int p = 0; p < 4; p++) { int pid = lane_px + 32 * p; pr[p] = pid >> 4; pc[p] = pid & 15; }

    float acc[8][4];
#pragma unroll
    for (int o = 0; o < 8; o++)
#pragma unroll
        for (int p = 0; p < 4; p++) acc[o][p] = 0.f;

    const float* xin = x + (size_t)img * 256 * HWp;

    for (int ic0 = 0; ic0 < 256; ic0 += 16) {
        __syncthreads();
        for (int l = tid; l < 16 * 180; l += 256) {
            int icj = l / 180; int rr = l % 180; int py = rr / 18; int px = rr % 18;
            int gy = y0 - 1 + py, gx = x0 - 1 + px;
            float v = 0.f;
            if (gy >= 0 && gy < H && gx >= 0 && gx < W)
                v = xin[(size_t)(ic0 + icj) * HWp + gy * W + gx];
            ins[(icj * 10 + py) * 18 + px] = v;
        }
        for (int l = tid; l < 64 * 16 * 9; l += 256) {
            int oci = l / 144; int rr = l % 144; int icj = rr / 9; int tap = rr % 9;
            wsm[(icj * 9 + tap) * 64 + oci] =
                cw[((size_t)(ocBase + oci) * 256 + ic0 + icj) * 9 + tap];
        }
        __syncthreads();

#pragma unroll 1
        for (int ic = 0; ic < 16; ic++) {
#pragma unroll
            for (int ky = 0; ky < 3; ky++) {
#pragma unroll
                for (int kx = 0; kx < 3; kx++) {
                    const float* wp = &wsm[(ic * 9 + ky * 3 + kx) * 64 + ocg * 8];
                    float wv[8];
#pragma unroll
                    for (int o = 0; o < 8; o++) wv[o] = wp[o];
                    float iv[4];
#pragma unroll
                    for (int p = 0; p < 4; p++)
                        iv[p] = ins[(ic * 10 + pr[p] + ky) * 18 + pc[p] + kx];
#pragma unroll
                    for (int o = 0; o < 8; o++)
#pragma unroll
                        for (int p = 0; p < 4; p++) acc[o][p] += wv[o] * iv[p];
                }
            }
        }
    }

#pragma unroll
    for (int o = 0; o < 8; o++) {
        int oc = ocBase + ocg * 8 + o;
        float bias = cb[oc];
#pragma unroll
        for (int p = 0; p < 4; p++) {
            int gy = y0 + pr[p], gx = x0 + pc[p];
            if (gy < H && gx < W) {
                float v = acc[o][p] + bias;
                g_h[hoff + ((size_t)img * 256 + oc) * HWp + (size_t)gy * W + gx] =
                    v > 0.f ? v : 0.f;
            }
        }
    }
}

// ---------------- heads: 15 dot products (3 logits + 12 reg) per pixel ----
__global__ void head_kernel(const float* __restrict__ lw, const float* __restrict__ lb,
                            const float* __restrict__ rw, const float* __restrict__ rb,
                            int HW, int aoff, int hoff) {
    __shared__ float wsm[15 * 256];
    __shared__ float red[8][32][16];

    const int tid = threadIdx.x;
    for (int l = tid; l < 15 * 256; l += 256) {
        int o = l >> 8, c = l & 255;
        wsm[l] = (o < 3) ? lw[o * 256 + c] : rw[(o - 3) * 256 + c];
    }
    __syncthreads();

    const int img = blockIdx.y;
    const int pix = blockIdx.x * 32 + (tid & 31);
    const int cg = tid >> 5;

    float acc[15];
#pragma unroll
    for (int o = 0; o < 15; o++) acc[o] = 0.f;

    if (pix < HW) {
        const float* hp = g_h + hoff + ((size_t)img * 256 + cg * 32) * HW + pix;
#pragma unroll 4
        for (int j = 0; j < 32; j++) {
            float v = hp[(size_t)j * HW];
            int c = cg * 32 + j;
#pragma unroll
            for (int o = 0; o < 15; o++) acc[o] += v * wsm[o * 256 + c];
        }
    }
#pragma unroll
    for (int o = 0; o < 15; o++) red[cg][tid & 31][o] = acc[o];
    __syncthreads();

    for (int l = tid; l < 32 * 15; l += 256) {
        int px = l / 15, o = l % 15;
        float s = 0.f;
#pragma unroll
        for (int g = 0; g < 8; g++) s += red[g][px][o];
        int p = blockIdx.x * 32 + px;
        if (p < HW) {
            if (o < 3) {
                g_logit[(size_t)img * DFULL + aoff + p * 3 + o] = s + lb[o];
            } else {
                int r = o - 3, a = r >> 2, comp = r & 3;
                g_reg[((size_t)img * DFULL + aoff + p * 3 + a) * 4 + comp] = s + rb[r];
            }
        }
    }
}

// ---------------- exact top-k (set + lowest-index ties) radix select ------
__device__ __forceinline__ unsigned fkey(float f) {
    unsigned u = __float_as_uint(f);
    return (u & 0x80000000u) ? ~u : (u | 0x80000000u);
}

__global__ void topk_kernel() {
    const int b = blockIdx.x;
    const int im = b / 5, lvl = b % 5;
    const int L = 3 * d_HW[lvl];
    const int K = d_K[lvl];
    const float* src = g_logit + (size_t)im * DFULL + d_AOFF[lvl];
    int* oidx = g_topidx + b * 1000;
    float* olog = g_toplog + b * 1000;
    const int tid = threadIdx.x;
    const int nth = blockDim.x;

    if (L <= K) {
        for (int i = tid; i < L; i += nth) { oidx[i] = i; olog[i] = src[i]; }
        return;
    }

    __shared__ unsigned hist[2048];
    __shared__ unsigned sfxA[2048];
    __shared__ unsigned sfxB[2048];
    __shared__ int eqlist[1024];
    __shared__ int sh_d, sh_sub, sh_cnt, sh_eq;

    unsigned prefix = 0;
    int bitsdone = 0;
    int krem = K;
    const int widths[3] = {11, 11, 10};

    for (int pass = 0; pass < 3; pass++) {
        int wb = widths[pass];
        int nb = 1 << wb;
        int shift = 32 - bitsdone - wb;
        for (int l = tid; l < nb; l += nth) hist[l] = 0;
        __syncthreads();
        for (int i = tid; i < L; i += nth) {
            unsigned u = fkey(src[i]);
            if (bitsdone == 0 || (u >> (32 - bitsdone)) == prefix)
                atomicAdd(&hist[(u >> shift) & (nb - 1)], 1u);
        }
        __syncthreads();
        unsigned* s = sfxA; unsigned* d = sfxB;
        for (int l = tid; l < nb; l += nth) s[l] = hist[l];
        for (int off = 1; off < nb; off <<= 1) {
            __syncthreads();
            for (int l = tid; l < nb; l += nth)
                d[l] = s[l] + ((l + off < nb) ? s[l + off] : 0u);
            unsigned* t = s; s = d; d = t;
        }
        __syncthreads();
        for (int l = tid; l < nb; l += nth) {
            unsigned ge = s[l];
            unsigned gt = (l + 1 < nb) ? s[l + 1] : 0u;
            if ((int)ge >= krem && (int)gt < krem) { sh_d = l; sh_sub = (int)gt; }
        }
        __syncthreads();
        prefix = (prefix << wb) | (unsigned)sh_d;
        krem -= sh_sub;
        bitsdone += wb;
        __syncthreads();
    }

    const unsigned T = prefix;  // key of the K-th largest element
    if (tid == 0) { sh_cnt = 0; sh_eq = 0; }
    __syncthreads();

    // collect indices of elements equal to the threshold key
    for (int i = tid; i < L; i += nth) {
        if (fkey(src[i]) == T) {
            int p = atomicAdd(&sh_eq, 1);
            if (p < 1024) eqlist[p] = i;
        }
    }
    __syncthreads();
    int m = sh_eq < 1024 ? sh_eq : 1024;
    for (int l = tid; l < 1024; l += nth)
        if (l >= m) eqlist[l] = 0x7FFFFFFF;
    __syncthreads();
    // sort equal-indices ascending (take the krem lowest, matching lax.top_k)
    for (int k = 2; k <= 1024; k <<= 1) {
        for (int j = k >> 1; j > 0; j >>= 1) {
            if (tid < 1024) {
                int ixj = tid ^ j;
                if (ixj > tid) {
                    int a = eqlist[tid], bb = eqlist[ixj];
                    bool asc = ((tid & k) == 0);
                    if (asc ? (a > bb) : (a < bb)) { eqlist[tid] = bb; eqlist[ixj] = a; }
                }
            }
            __syncthreads();
        }
    }

    for (int i = tid; i < L; i += nth) {
        float f = src[i];
        if (fkey(f) > T) {
            int p = atomicAdd(&sh_cnt, 1);
            oidx[p] = i; olog[p] = f;
        }
    }
    __syncthreads();
    for (int l = tid; l < krem; l += nth) {
        int i = eqlist[l];
        int p = atomicAdd(&sh_cnt, 1);
        oidx[p] = i; olog[p] = src[i];
    }
}

// ---- sort each group's selection by (logit desc, index asc) --------------
// After this, slot order == reference's lax.top_k output order (D-indexing).
__global__ void sortsel_kernel() {
    __shared__ float skey[1024];
    __shared__ int sidx[1024];
    const int b = blockIdx.x;
    const int K = d_K[b % 5];
    const int tid = threadIdx.x;

    float k = -FLT_MAX; int ix = 0x7FFFFFFF;
    if (tid < K) { k = g_toplog[b * 1000 + tid]; ix = g_topidx[b * 1000 + tid]; }
    skey[tid] = k; sidx[tid] = ix;
    __syncthreads();

    for (int kk = 2; kk <= 1024; kk <<= 1) {
        for (int j = kk >> 1; j > 0; j >>= 1) {
            int ixj = tid ^ j;
            if (ixj > tid) {
                float ka = skey[tid], kb = skey[ixj];
                int ia = sidx[tid], ib = sidx[ixj];
                bool aGb = (ka > kb) || (ka == kb && ia < ib);
                bool desc = ((tid & kk) == 0);
                if (desc ? !aGb : aGb) {
                    skey[tid] = kb; skey[ixj] = ka;
                    sidx[tid] = ib; sidx[ixj] = ia;
                }
            }
            __syncthreads();
        }
    }
    if (tid < K) { g_toplog[b * 1000 + tid] = skey[tid]; g_topidx[b * 1000 + tid] = sidx[tid]; }
}

// ---------------- decode + clip + validity + sigmoid + global max --------
__global__ void maxinit_kernel() { g_maxbits = 0u; }

__global__ void decode_kernel(const float* __restrict__ p0, const float* __restrict__ p1,
                              const float* __restrict__ p2, const float* __restrict__ p3,
                              const float* __restrict__ p4, const float* __restrict__ imsz) {
    int q = blockIdx.x * blockDim.x + threadIdx.x;
    if (q >= NTOT) return;
    int im = q / DSEL;
    int r = q % DSEL;
    int lvl = (r < 1000) ? 0 : (r < 2000) ? 1 : (r < 3000) ? 2 : (r < 3741) ? 3 : 4;
    int slot = r - d_COFF[lvl];
    int g = (im * 5 + lvl) * 1000 + slot;
    int idx = g_topidx[g];
    float logit = g_toplog[g];

    const float* pri =
        ((lvl == 0) ? p0 : (lvl == 1) ? p1 : (lvl == 2) ? p2 : (lvl == 3) ? p3 : p4) +
        (size_t)idx * 4;
    size_t rb = ((size_t)im * DFULL + d_AOFF[lvl] + idx) * 4;

    float dx = g_reg[rb + 0], dy = g_reg[rb + 1];
    float dw = fminf(g_reg[rb + 2], LOG_MAXF);
    float dh = fminf(g_reg[rb + 3], LOG_MAXF);
    float pcx = pri[0], pcy = pri[1], pw = pri[2], ph = pri[3];
    float cx = dx * pw + pcx, cy = dy * ph + pcy;
    float w = pw * expf(dw), h = ph * expf(dh);
    float x1 = cx - 0.5f * w, y1 = cy - 0.5f * h;
    float x2 = cx + 0.5f * w, y2 = cy + 0.5f * h;
    float Wc = imsz[im * 2 + 1], Hc = imsz[im * 2 + 0];
    x1 = fminf(fmaxf(x1, 0.f), Wc); x2 = fminf(fmaxf(x2, 0.f), Wc);
    y1 = fminf(fmaxf(y1, 0.f), Hc); y2 = fminf(fmaxf(y2, 0.f), Hc);

    g_cbox[q] = make_float4(x1, y1, x2, y2);
    g_cscore[q] = 1.f / (1.f + expf(-logit));
    g_cvalid[q] = ((x2 - x1) >= 0.001f) && ((y2 - y1) >= 0.001f);
    g_csc[q] = -1.0f;   // default: not kept

    // contribute to global max coordinate (all coords >= 0 -> uint-monotone)
    float m4 = fmaxf(fmaxf(x1, y1), fmaxf(x2, y2));
    atomicMax(&g_maxbits, __float_as_uint(m4));
}

// ---------------- per-group NMS: stable sort + bit-exact shifted IoU ------
__global__ void nms_kernel() {
    __shared__ float skey[1024];
    __shared__ int sidx[1024];
    __shared__ float4 sbox[1024];    // SHIFTED boxes (reference rounding)
    __shared__ float sarea[1024];    // areas of shifted boxes
    __shared__ unsigned char srem[1024];

    const int b = blockIdx.x;
    const int im = b / 5, lvl = b % 5;
    const int base = im * DSEL + d_COFF[lvl];
    const int cnt = d_K[lvl];
    const int tid = threadIdx.x;

    float sc = -FLT_MAX;
    if (tid < cnt && g_cvalid[base + tid]) sc = g_cscore[base + tid];
    skey[tid] = sc;
    sidx[tid] = tid;

    // bitonic sort: (score desc, index asc) == stable argsort(-s)
    for (int k = 2; k <= 1024; k <<= 1) {
        for (int j = k >> 1; j > 0; j >>= 1) {
            __syncthreads();
            int ixj = tid ^ j;
            if (ixj > tid) {
                float ka = skey[tid], kb = skey[ixj];
                int ia = sidx[tid], ib = sidx[ixj];
                bool aGb = (ka > kb) || (ka == kb && ia < ib);
                bool desc = ((tid & k) == 0);
                if (desc ? !aGb : aGb) {
                    skey[tid] = kb; skey[ixj] = ka;
                    sidx[tid] = ib; sidx[ixj] = ia;
                }
            }
        }
    }
    __syncthreads();

    // reference shifts boxes by group*(max+1) BEFORE IoU; the fp32 rounding of
    // that shift quantizes coords (~5e-4 at offset ~8.5k) and flips threshold
    // decisions. Replicate bit-for-bit with explicit round-to-nearest ops.
    {
        float M = __uint_as_float(g_maxbits);
        float off = __fmul_rn((float)(im * 10 + lvl), __fadd_rn(M, 1.0f));
        if (skey[tid] > -1e37f) {
            float4 bx = g_cbox[base + sidx[tid]];
            float sx1 = __fadd_rn(bx.x, off), sy1 = __fadd_rn(bx.y, off);
            float sx2 = __fadd_rn(bx.z, off), sy2 = __fadd_rn(bx.w, off);
            sbox[tid] = make_float4(sx1, sy1, sx2, sy2);
            sarea[tid] = __fmul_rn(__fsub_rn(sx2, sx1), __fsub_rn(sy2, sy1));
        } else {
            sbox[tid] = make_float4(0.f, 0.f, 0.f, 0.f);
            sarea[tid] = 0.f;
        }
        srem[tid] = 0;
    }
    __syncthreads();

    for (int i = 0; i < cnt; i++) {
        if (skey[i] <= -1e37f) break;  // rest are invalid/padding
        bool alive = (srem[i] == 0);
        if (alive && tid > i && srem[tid] == 0 && skey[tid] > -1e37f) {
            float4 A = sbox[i], B = sbox[tid];
            float lx = fmaxf(A.x, B.x), ly = fmaxf(A.y, B.y);
            float rx = fminf(A.z, B.z), ry = fminf(A.w, B.w);
            float w = fmaxf(__fsub_rn(rx, lx), 0.f);
            float h = fmaxf(__fsub_rn(ry, ly), 0.f);
            float inter = __fmul_rn(w, h);
            // reference: inter / ((ac + area) - inter + 1e-9)
            float denom = __fadd_rn(__fsub_rn(__fadd_rn(sarea[i], sarea[tid]), inter), 1e-9f);
            float iou = __fdiv_rn(inter, denom);
            if (iou > 0.7f) srem[tid] = 1;
        }
        __syncthreads();
    }

    if (skey[tid] > -1e37f && srem[tid] == 0 && sidx[tid] < cnt) {
        g_csc[base + sidx[tid]] = skey[tid];
    }
}

// ---------------- final: per-image stable sort, emit top-1000 -------------
__global__ void final_kernel(float* __restrict__ out) {
    __shared__ float skey[4096];
    __shared__ int sidx[4096];
    const int im = blockIdx.x;
    const int tid = threadIdx.x;

    for (int e = 0; e < 4; e++) {
        int i = tid + e * 1024;
        float v = -3.0f;
        if (i < DSEL) v = g_csc[im * DSEL + i];
        skey[i] = v;
        sidx[i] = i;
    }
    __syncthreads();

    for (int k = 2; k <= 4096; k <<= 1) {
        for (int j = k >> 1; j > 0; j >>= 1) {
            for (int e = 0; e < 4; e++) {
                int i = tid + e * 1024;
                int ixj = i ^ j;
                if (ixj > i) {
                    float ka = skey[i], kb = skey[ixj];
                    int ia = sidx[i], ib = sidx[ixj];
                    bool aGb = (ka > kb) || (ka == kb && ia < ib);
                    bool desc = ((i & k) == 0);
                    if (desc ? !aGb : aGb) {
                        skey[i] = kb; skey[ixj] = ka;
                        sidx[i] = ib; sidx[ixj] = ia;
                    }
                }
            }
            __syncthreads();
        }
    }

    if (tid < 1000) {
        float v = skey[tid];
        float* o = out + ((size_t)im * 1000 + tid) * 5;
        if (v > -0.5f) {
            float4 bx = g_cbox[im * DSEL + sidx[tid]];
            o[0] = bx.x; o[1] = bx.y; o[2] = bx.z; o[3] = bx.w; o[4] = v;
        } else {
            o[0] = 0.f; o[1] = 0.f; o[2] = 0.f; o[3] = 0.f; o[4] = 0.f;
        }
    }
}

// ---------------- launch ---------------------------------------------------
extern "C" void kernel_launch(void* const* d_in, const int* in_sizes, int n_in,
                              void* d_out, int out_size) {
    const float *fm[5] = {0, 0, 0, 0, 0}, *pr[5] = {0, 0, 0, 0, 0};
    const float *imsz = 0, *cw = 0, *cb = 0, *lw = 0, *lb = 0, *rw = 0, *rbv = 0;
    for (int i = 0; i < n_in; i++) {
        const float* p = (const float*)d_in[i];
        switch (in_sizes[i]) {
            case 7782400: fm[0] = p; break;
            case 1945600: fm[1] = p; break;
            case 486400:  fm[2] = p; break;
            case 126464:  fm[3] = p; break;
            case 35840:   fm[4] = p; break;
            case 182400:  pr[0] = p; break;
            case 45600:   pr[1] = p; break;
            case 11400:   pr[2] = p; break;
            case 2964:    pr[3] = p; break;
            case 840:     pr[4] = p; break;
            case 4:       imsz = p; break;
            case 589824:  cw = p; break;
            case 256:     cb = p; break;
            case 768:     lw = p; break;
            case 3:       lb = p; break;
            case 3072:    rw = p; break;
            case 12:      rbv = p; break;
            default: break;  // lvtop/imtop (size 1) — fixed at 1000, baked in
        }
    }

    static const int hH[5]    = {100, 50, 25, 13, 7};
    static const int hWd[5]   = {152, 76, 38, 19, 10};
    static const int hHW[5]   = {15200, 3800, 950, 247, 70};
    static const int hHOFF[5] = {0, 7782400, 9728000, 10214400, 10340864};
    static const int hAOFF[5] = {0, 45600, 57000, 59850, 60591};

    for (int l = 0; l < 5; l++) {
        dim3 grid((hWd[l] + 15) / 16, (hH[l] + 7) / 8, 8);
        conv_kernel<<<grid, 256>>>(fm[l], cw, cb, hH[l], hWd[l], hHOFF[l]);
    }
    for (int l = 0; l < 5; l++) {
        dim3 grid((hHW[l] + 31) / 32, 2);
        head_kernel<<<grid, 256>>>(lw, lb, rw, rbv, hHW[l], hAOFF[l], hHOFF[l]);
    }
    topk_kernel<<<10, 1024>>>();
    sortsel_kernel<<<10, 1024>>>();
    maxinit_kernel<<<1, 1>>>();
    decode_kernel<<<(NTOT + 255) / 256, 256>>>(pr[0], pr[1], pr[2], pr[3], pr[4], imsz);
    nms_kernel<<<10, 1024>>>();
    final_kernel<<<2, 1024>>>((float*)d_out);
}

// round 6
// speedup vs baseline: 1.3243x; 1.3243x over previous
#include <cuda_runtime.h>
#include <math.h>
#include <float.h>

// ---------------- problem constants (fixed by setup_inputs) ----------------
#define DFULL 60801
#define DSEL  3951
#define NTOT  7902
#define LOG_MAXF 4.135166556742356f

__device__ const int d_HW[5]   = {15200, 3800, 950, 247, 70};
__device__ const int d_K[5]    = {1000, 1000, 1000, 741, 210};
__device__ const int d_AOFF[5] = {0, 45600, 57000, 59850, 60591};
__device__ const int d_COFF[5] = {0, 1000, 2000, 3000, 3741};

// conv merged-launch level decode tables
__device__ const int c_LB[5]   = {0, 1040, 1320, 1416, 1448};   // block offsets
__device__ const int c_NTX[5]  = {10, 5, 3, 2, 1};
__device__ const int c_NTY[5]  = {13, 7, 4, 2, 1};
__device__ const int c_H[5]    = {100, 50, 25, 13, 7};
__device__ const int c_W[5]    = {152, 76, 38, 19, 10};
__device__ const int c_HOFF[5] = {0, 7782400, 9728000, 10214400, 10340864};
// head merged-launch tables
__device__ const int h_HB[5]   = {0, 475, 594, 624, 632};       // block offsets (x)

// ---------------- scratch (static device memory; no allocs) ----------------
__device__ float    g_h[10376704];
__device__ float    g_logit[2 * DFULL];
__device__ float    g_reg[2 * DFULL * 4];
__device__ int      g_topidx[10 * 1000];
__device__ float    g_toplog[10 * 1000];
__device__ float4   g_cbox[NTOT];
__device__ float    g_cscore[NTOT];
__device__ int      g_cvalid[NTOT];
__device__ float    g_csc[NTOT];
__device__ unsigned g_maxbits;

// ---------------- conv 3x3 (SAME) + bias + relu, ALL levels in one grid ---
// block: 256 thr = 8 ocGroups x 32 pxGroups; tile 64 oc x (8 rows x 16 cols)
// thread: 8 oc x 4 consecutive cols; per-ic register row cache riv[3][6]
__global__ __launch_bounds__(256, 2)
void conv_kernel(const float* __restrict__ f0, const float* __restrict__ f1,
                 const float* __restrict__ f2, const float* __restrict__ f3,
                 const float* __restrict__ f4,
                 const float* __restrict__ cw, const float* __restrict__ cb) {
    __shared__ float ins[8 * 10 * 20];   // 8 ic x (8+2) rows x stride-20 cols
    __shared__ float wsm[8 * 9 * 64];    // 8 ic x 9 taps x 64 oc

    const int b = blockIdx.x;
    const int lvl = (b < 1040) ? 0 : (b < 1320) ? 1 : (b < 1416) ? 2 : (b < 1448) ? 3 : 4;
    const int r = b - c_LB[lvl];
    const int ntx = c_NTX[lvl];
    const int nt = ntx * c_NTY[lvl];
    const int z = r / nt;
    const int rr = r % nt;
    const int ty = rr / ntx, tx = rr % ntx;
    const int img = z >> 2;
    const int ocBase = (z & 3) * 64;
    const int H = c_H[lvl], W = c_W[lvl];
    const int HWp = H * W;
    const int hoff = c_HOFF[lvl];
    const float* xin =
        ((lvl == 0) ? f0 : (lvl == 1) ? f1 : (lvl == 2) ? f2 : (lvl == 3) ? f3 : f4)
        + (size_t)img * 256 * HWp;

    const int tid = threadIdx.x;
    const int ocg = tid >> 5;          // 0..7 (uniform within warp)
    const int g = tid & 31;            // pixel group
    const int row = g >> 2;            // 0..7
    const int cg = g & 3;              // 0..3 -> cols cg*4 .. cg*4+3
    const int x0 = tx * 16, y0 = ty * 8;

    float acc[8][4];
#pragma unroll
    for (int o = 0; o < 8; o++)
#pragma unroll
        for (int p = 0; p < 4; p++) acc[o][p] = 0.f;

    for (int ic0 = 0; ic0 < 256; ic0 += 8) {
        __syncthreads();
        // stage input patch: 8 ic x 10 rows x 18 cols (stride 20, zero-pad SAME)
        for (int l = tid; l < 8 * 180; l += 256) {
            int icj = l / 180; int q = l % 180; int py = q / 18; int px = q % 18;
            int gy = y0 - 1 + py, gx = x0 - 1 + px;
            float v = 0.f;
            if (gy >= 0 && gy < H && gx >= 0 && gx < W)
                v = xin[(size_t)(ic0 + icj) * HWp + gy * W + gx];
            ins[(icj * 10 + py) * 20 + px] = v;
        }
        // stage weights: 8 ic x 9 taps x 64 oc
        for (int l = tid; l < 8 * 9 * 64; l += 256) {
            int oci = l / 72; int q = l % 72; int icj = q / 9; int tap = q % 9;
            wsm[(icj * 9 + tap) * 64 + oci] =
                cw[((size_t)(ocBase + oci) * 256 + ic0 + icj) * 9 + tap];
        }
        __syncthreads();

#pragma unroll 1
        for (int ic = 0; ic < 8; ic++) {
            const float* bp = &ins[(ic * 10 + row) * 20 + cg * 4];
            float riv[3][6];
#pragma unroll
            for (int ky = 0; ky < 3; ky++) {
                float4 v4 = *(const float4*)(bp + ky * 20);
                float2 v2 = *(const float2*)(bp + ky * 20 + 4);
                riv[ky][0] = v4.x; riv[ky][1] = v4.y; riv[ky][2] = v4.z; riv[ky][3] = v4.w;
                riv[ky][4] = v2.x; riv[ky][5] = v2.y;
            }
#pragma unroll
            for (int ky = 0; ky < 3; ky++) {
#pragma unroll
                for (int kx = 0; kx < 3; kx++) {
                    const float* wp = &wsm[(ic * 9 + ky * 3 + kx) * 64 + ocg * 8];
                    float4 wa = *(const float4*)wp;
                    float4 wb = *(const float4*)(wp + 4);
                    float wv[8] = {wa.x, wa.y, wa.z, wa.w, wb.x, wb.y, wb.z, wb.w};
#pragma unroll
                    for (int o = 0; o < 8; o++)
#pragma unroll
                        for (int p = 0; p < 4; p++)
                            acc[o][p] += wv[o] * riv[ky][kx + p];
                }
            }
        }
    }

    // epilogue: bias + relu + store
    const int gy = y0 + row;
    if (gy < H) {
#pragma unroll
        for (int o = 0; o < 8; o++) {
            int oc = ocBase + ocg * 8 + o;
            float bias = cb[oc];
            float* dst = &g_h[hoff + ((size_t)img * 256 + oc) * HWp + (size_t)gy * W];
#pragma unroll
            for (int p = 0; p < 4; p++) {
                int gx = x0 + cg * 4 + p;
                if (gx < W) {
                    float v = acc[o][p] + bias;
                    dst[gx] = v > 0.f ? v : 0.f;
                }
            }
        }
    }
}

// ---------------- heads: 15 dot products per pixel, ALL levels one grid ---
__global__ void head_kernel(const float* __restrict__ lw, const float* __restrict__ lb,
                            const float* __restrict__ rw, const float* __restrict__ rb) {
    __shared__ float wsm[15 * 256];
    __shared__ float red[8][32][16];

    const int bx = blockIdx.x;
    const int lvl = (bx < 475) ? 0 : (bx < 594) ? 1 : (bx < 624) ? 2 : (bx < 632) ? 3 : 4;
    const int lb_blk = bx - h_HB[lvl];
    const int HW = d_HW[lvl];
    const int aoff = d_AOFF[lvl];
    const int hoff = c_HOFF[lvl];

    const int tid = threadIdx.x;
    for (int l = tid; l < 15 * 256; l += 256) {
        int o = l >> 8, c = l & 255;
        wsm[l] = (o < 3) ? lw[o * 256 + c] : rw[(o - 3) * 256 + c];
    }
    __syncthreads();

    const int img = blockIdx.y;
    const int pix = lb_blk * 32 + (tid & 31);
    const int cg = tid >> 5;

    float acc[15];
#pragma unroll
    for (int o = 0; o < 15; o++) acc[o] = 0.f;

    if (pix < HW) {
        const float* hp = g_h + hoff + ((size_t)img * 256 + cg * 32) * HW + pix;
#pragma unroll 4
        for (int j = 0; j < 32; j++) {
            float v = hp[(size_t)j * HW];
            int c = cg * 32 + j;
#pragma unroll
            for (int o = 0; o < 15; o++) acc[o] += v * wsm[o * 256 + c];
        }
    }
#pragma unroll
    for (int o = 0; o < 15; o++) red[cg][tid & 31][o] = acc[o];
    __syncthreads();

    for (int l = tid; l < 32 * 15; l += 256) {
        int px = l / 15, o = l % 15;
        float s = 0.f;
#pragma unroll
        for (int g = 0; g < 8; g++) s += red[g][px][o];
        int p = lb_blk * 32 + px;
        if (p < HW) {
            if (o < 3) {
                g_logit[(size_t)img * DFULL + aoff + p * 3 + o] = s + lb[o];
            } else {
                int rr = o - 3, a = rr >> 2, comp = rr & 3;
                g_reg[((size_t)img * DFULL + aoff + p * 3 + a) * 4 + comp] = s + rb[rr];
            }
        }
    }
}

// ---------------- exact top-k (set + lowest-index ties) radix select ------
__device__ __forceinline__ unsigned fkey(float f) {
    unsigned u = __float_as_uint(f);
    return (u & 0x80000000u) ? ~u : (u | 0x80000000u);
}

__global__ void topk_kernel() {
    const int b = blockIdx.x;
    const int im = b / 5, lvl = b % 5;
    const int L = 3 * d_HW[lvl];
    const int K = d_K[lvl];
    const float* src = g_logit + (size_t)im * DFULL + d_AOFF[lvl];
    int* oidx = g_topidx + b * 1000;
    float* olog = g_toplog + b * 1000;
    const int tid = threadIdx.x;
    const int nth = blockDim.x;

    if (L <= K) {
        for (int i = tid; i < L; i += nth) { oidx[i] = i; olog[i] = src[i]; }
        return;
    }

    __shared__ unsigned hist[2048];
    __shared__ unsigned sfxA[2048];
    __shared__ unsigned sfxB[2048];
    __shared__ int eqlist[1024];
    __shared__ int sh_d, sh_sub, sh_cnt, sh_eq;

    unsigned prefix = 0;
    int bitsdone = 0;
    int krem = K;
    const int widths[3] = {11, 11, 10};

    for (int pass = 0; pass < 3; pass++) {
        int wb = widths[pass];
        int nb = 1 << wb;
        int shift = 32 - bitsdone - wb;
        for (int l = tid; l < nb; l += nth) hist[l] = 0;
        __syncthreads();
        for (int i = tid; i < L; i += nth) {
            unsigned u = fkey(src[i]);
            if (bitsdone == 0 || (u >> (32 - bitsdone)) == prefix)
                atomicAdd(&hist[(u >> shift) & (nb - 1)], 1u);
        }
        __syncthreads();
        unsigned* s = sfxA; unsigned* d = sfxB;
        for (int l = tid; l < nb; l += nth) s[l] = hist[l];
        for (int off = 1; off < nb; off <<= 1) {
            __syncthreads();
            for (int l = tid; l < nb; l += nth)
                d[l] = s[l] + ((l + off < nb) ? s[l + off] : 0u);
            unsigned* t = s; s = d; d = t;
        }
        __syncthreads();
        for (int l = tid; l < nb; l += nth) {
            unsigned ge = s[l];
            unsigned gt = (l + 1 < nb) ? s[l + 1] : 0u;
            if ((int)ge >= krem && (int)gt < krem) { sh_d = l; sh_sub = (int)gt; }
        }
        __syncthreads();
        prefix = (prefix << wb) | (unsigned)sh_d;
        krem -= sh_sub;
        bitsdone += wb;
        __syncthreads();
    }

    const unsigned T = prefix;
    if (tid == 0) { sh_cnt = 0; sh_eq = 0; }
    __syncthreads();

    for (int i = tid; i < L; i += nth) {
        if (fkey(src[i]) == T) {
            int p = atomicAdd(&sh_eq, 1);
            if (p < 1024) eqlist[p] = i;
        }
    }
    __syncthreads();
    int m = sh_eq < 1024 ? sh_eq : 1024;
    for (int l = tid; l < 1024; l += nth)
        if (l >= m) eqlist[l] = 0x7FFFFFFF;
    __syncthreads();
    for (int k = 2; k <= 1024; k <<= 1) {
        for (int j = k >> 1; j > 0; j >>= 1) {
            if (tid < 1024) {
                int ixj = tid ^ j;
                if (ixj > tid) {
                    int a = eqlist[tid], bb = eqlist[ixj];
                    bool asc = ((tid & k) == 0);
                    if (asc ? (a > bb) : (a < bb)) { eqlist[tid] = bb; eqlist[ixj] = a; }
                }
            }
            __syncthreads();
        }
    }

    for (int i = tid; i < L; i += nth) {
        float f = src[i];
        if (fkey(f) > T) {
            int p = atomicAdd(&sh_cnt, 1);
            oidx[p] = i; olog[p] = f;
        }
    }
    __syncthreads();
    for (int l = tid; l < krem; l += nth) {
        int i = eqlist[l];
        int p = atomicAdd(&sh_cnt, 1);
        oidx[p] = i; olog[p] = src[i];
    }
}

// ---- sort each group's selection by (logit desc, index asc) --------------
__global__ void sortsel_kernel() {
    __shared__ float skey[1024];
    __shared__ int sidx[1024];
    const int b = blockIdx.x;
    const int K = d_K[b % 5];
    const int tid = threadIdx.x;

    float k = -FLT_MAX; int ix = 0x7FFFFFFF;
    if (tid < K) { k = g_toplog[b * 1000 + tid]; ix = g_topidx[b * 1000 + tid]; }
    skey[tid] = k; sidx[tid] = ix;
    __syncthreads();

    for (int kk = 2; kk <= 1024; kk <<= 1) {
        for (int j = kk >> 1; j > 0; j >>= 1) {
            int ixj = tid ^ j;
            if (ixj > tid) {
                float ka = skey[tid], kb = skey[ixj];
                int ia = sidx[tid], ib = sidx[ixj];
                bool aGb = (ka > kb) || (ka == kb && ia < ib);
                bool desc = ((tid & kk) == 0);
                if (desc ? !aGb : aGb) {
                    skey[tid] = kb; skey[ixj] = ka;
                    sidx[tid] = ib; sidx[ixj] = ia;
                }
            }
            __syncthreads();
        }
    }
    if (tid < K) { g_toplog[b * 1000 + tid] = skey[tid]; g_topidx[b * 1000 + tid] = sidx[tid]; }
}

// ---------------- decode + clip + validity + sigmoid + global max --------
__global__ void maxinit_kernel() { g_maxbits = 0u; }

__global__ void decode_kernel(const float* __restrict__ p0, const float* __restrict__ p1,
                              const float* __restrict__ p2, const float* __restrict__ p3,
                              const float* __restrict__ p4, const float* __restrict__ imsz) {
    int q = blockIdx.x * blockDim.x + threadIdx.x;
    if (q >= NTOT) return;
    int im = q / DSEL;
    int r = q % DSEL;
    int lvl = (r < 1000) ? 0 : (r < 2000) ? 1 : (r < 3000) ? 2 : (r < 3741) ? 3 : 4;
    int slot = r - d_COFF[lvl];
    int g = (im * 5 + lvl) * 1000 + slot;
    int idx = g_topidx[g];
    float logit = g_toplog[g];

    const float* pri =
        ((lvl == 0) ? p0 : (lvl == 1) ? p1 : (lvl == 2) ? p2 : (lvl == 3) ? p3 : p4) +
        (size_t)idx * 4;
    size_t rb = ((size_t)im * DFULL + d_AOFF[lvl] + idx) * 4;

    float dx = g_reg[rb + 0], dy = g_reg[rb + 1];
    float dw = fminf(g_reg[rb + 2], LOG_MAXF);
    float dh = fminf(g_reg[rb + 3], LOG_MAXF);
    float pcx = pri[0], pcy = pri[1], pw = pri[2], ph = pri[3];
    float cx = dx * pw + pcx, cy = dy * ph + pcy;
    float w = pw * expf(dw), h = ph * expf(dh);
    float x1 = cx - 0.5f * w, y1 = cy - 0.5f * h;
    float x2 = cx + 0.5f * w, y2 = cy + 0.5f * h;
    float Wc = imsz[im * 2 + 1], Hc = imsz[im * 2 + 0];
    x1 = fminf(fmaxf(x1, 0.f), Wc); x2 = fminf(fmaxf(x2, 0.f), Wc);
    y1 = fminf(fmaxf(y1, 0.f), Hc); y2 = fminf(fmaxf(y2, 0.f), Hc);

    g_cbox[q] = make_float4(x1, y1, x2, y2);
    g_cscore[q] = 1.f / (1.f + expf(-logit));
    g_cvalid[q] = ((x2 - x1) >= 0.001f) && ((y2 - y1) >= 0.001f);
    g_csc[q] = -1.0f;

    float m4 = fmaxf(fmaxf(x1, y1), fmaxf(x2, y2));
    atomicMax(&g_maxbits, __float_as_uint(m4));
}

// ---------------- per-group NMS: stable sort + bit-exact shifted IoU ------
__global__ void nms_kernel() {
    __shared__ float skey[1024];
    __shared__ int sidx[1024];
    __shared__ float4 sbox[1024];
    __shared__ float sarea[1024];
    __shared__ unsigned char srem[1024];

    const int b = blockIdx.x;
    const int im = b / 5, lvl = b % 5;
    const int base = im * DSEL + d_COFF[lvl];
    const int cnt = d_K[lvl];
    const int tid = threadIdx.x;

    float sc = -FLT_MAX;
    if (tid < cnt && g_cvalid[base + tid]) sc = g_cscore[base + tid];
    skey[tid] = sc;
    sidx[tid] = tid;

    for (int k = 2; k <= 1024; k <<= 1) {
        for (int j = k >> 1; j > 0; j >>= 1) {
            __syncthreads();
            int ixj = tid ^ j;
            if (ixj > tid) {
                float ka = skey[tid], kb = skey[ixj];
                int ia = sidx[tid], ib = sidx[ixj];
                bool aGb = (ka > kb) || (ka == kb && ia < ib);
                bool desc = ((tid & k) == 0);
                if (desc ? !aGb : aGb) {
                    skey[tid] = kb; skey[ixj] = ka;
                    sidx[tid] = ib; sidx[ixj] = ia;
                }
            }
        }
    }
    __syncthreads();

    {
        float M = __uint_as_float(g_maxbits);
        float off = __fmul_rn((float)(im * 10 + lvl), __fadd_rn(M, 1.0f));
        if (skey[tid] > -1e37f) {
            float4 bx = g_cbox[base + sidx[tid]];
            float sx1 = __fadd_rn(bx.x, off), sy1 = __fadd_rn(bx.y, off);
            float sx2 = __fadd_rn(bx.z, off), sy2 = __fadd_rn(bx.w, off);
            sbox[tid] = make_float4(sx1, sy1, sx2, sy2);
            sarea[tid] = __fmul_rn(__fsub_rn(sx2, sx1), __fsub_rn(sy2, sy1));
        } else {
            sbox[tid] = make_float4(0.f, 0.f, 0.f, 0.f);
            sarea[tid] = 0.f;
        }
        srem[tid] = 0;
    }
    __syncthreads();

    for (int i = 0; i < cnt; i++) {
        if (skey[i] <= -1e37f) break;
        bool alive = (srem[i] == 0);
        if (alive && tid > i && srem[tid] == 0 && skey[tid] > -1e37f) {
            float4 A = sbox[i], B = sbox[tid];
            float lx = fmaxf(A.x, B.x), ly = fmaxf(A.y, B.y);
            float rx = fminf(A.z, B.z), ry = fminf(A.w, B.w);
            float w = fmaxf(__fsub_rn(rx, lx), 0.f);
            float h = fmaxf(__fsub_rn(ry, ly), 0.f);
            float inter = __fmul_rn(w, h);
            float denom = __fadd_rn(__fsub_rn(__fadd_rn(sarea[i], sarea[tid]), inter), 1e-9f);
            float iou = __fdiv_rn(inter, denom);
            if (iou > 0.7f) srem[tid] = 1;
        }
        __syncthreads();
    }

    if (skey[tid] > -1e37f && srem[tid] == 0 && sidx[tid] < cnt) {
        g_csc[base + sidx[tid]] = skey[tid];
    }
}

// ---------------- final: per-image stable sort, emit top-1000 -------------
__global__ void final_kernel(float* __restrict__ out) {
    __shared__ float skey[4096];
    __shared__ int sidx[4096];
    const int im = blockIdx.x;
    const int tid = threadIdx.x;

    for (int e = 0; e < 4; e++) {
        int i = tid + e * 1024;
        float v = -3.0f;
        if (i < DSEL) v = g_csc[im * DSEL + i];
        skey[i] = v;
        sidx[i] = i;
    }
    __syncthreads();

    for (int k = 2; k <= 4096; k <<= 1) {
        for (int j = k >> 1; j > 0; j >>= 1) {
            for (int e = 0; e < 4; e++) {
                int i = tid + e * 1024;
                int ixj = i ^ j;
                if (ixj > i) {
                    float ka = skey[i], kb = skey[ixj];
                    int ia = sidx[i], ib = sidx[ixj];
                    bool aGb = (ka > kb) || (ka == kb && ia < ib);
                    bool desc = ((i & k) == 0);
                    if (desc ? !aGb : aGb) {
                        skey[i] = kb; skey[ixj] = ka;
                        sidx[i] = ib; sidx[ixj] = ia;
                    }
                }
            }
            __syncthreads();
        }
    }

    if (tid < 1000) {
        float v = skey[tid];
        float* o = out + ((size_t)im * 1000 + tid) * 5;
        if (v > -0.5f) {
            float4 bx = g_cbox[im * DSEL + sidx[tid]];
            o[0] = bx.x; o[1] = bx.y; o[2] = bx.z; o[3] = bx.w; o[4] = v;
        } else {
            o[0] = 0.f; o[1] = 0.f; o[2] = 0.f; o[3] = 0.f; o[4] = 0.f;
        }
    }
}

// ---------------- launch ---------------------------------------------------
extern "C" void kernel_launch(void* const* d_in, const int* in_sizes, int n_in,
                              void* d_out, int out_size) {
    const float *fm[5] = {0, 0, 0, 0, 0}, *pr[5] = {0, 0, 0, 0, 0};
    const float *imsz = 0, *cw = 0, *cb = 0, *lw = 0, *lb = 0, *rw = 0, *rbv = 0;
    for (int i = 0; i < n_in; i++) {
        const float* p = (const float*)d_in[i];
        switch (in_sizes[i]) {
            case 7782400: fm[0] = p; break;
            case 1945600: fm[1] = p; break;
            case 486400:  fm[2] = p; break;
            case 126464:  fm[3] = p; break;
            case 35840:   fm[4] = p; break;
            case 182400:  pr[0] = p; break;
            case 45600:   pr[1] = p; break;
            case 11400:   pr[2] = p; break;
            case 2964:    pr[3] = p; break;
            case 840:     pr[4] = p; break;
            case 4:       imsz = p; break;
            case 589824:  cw = p; break;
            case 256:     cb = p; break;
            case 768:     lw = p; break;
            case 3:       lb = p; break;
            case 3072:    rw = p; break;
            case 12:      rbv = p; break;
            default: break;
        }
    }

    conv_kernel<<<1456, 256>>>(fm[0], fm[1], fm[2], fm[3], fm[4], cw, cb);
    head_kernel<<<dim3(635, 2), 256>>>(lw, lb, rw, rbv);
    topk_kernel<<<10, 1024>>>();
    sortsel_kernel<<<10, 1024>>>();
    maxinit_kernel<<<1, 1>>>();
    decode_kernel<<<(NTOT + 255) / 256, 256>>>(pr[0], pr[1], pr[2], pr[3], pr[4], imsz);
    nms_kernel<<<10, 1024>>>();
    final_kernel<<<2, 1024>>>((float*)d_out);
}

// round 8
// speedup vs baseline: 1.3854x; 1.0462x over previous
#include <cuda_runtime.h>
#include <math.h>
#include <float.h>

// ---------------- problem constants (fixed by setup_inputs) ----------------
#define DFULL 60801
#define DSEL  3951
#define NTOT  7902
#define LOG_MAXF 4.135166556742356f

__device__ const int d_HW[5]   = {15200, 3800, 950, 247, 70};
__device__ const int d_K[5]    = {1000, 1000, 1000, 741, 210};
__device__ const int d_AOFF[5] = {0, 45600, 57000, 59850, 60591};
__device__ const int d_COFF[5] = {0, 1000, 2000, 3000, 3741};

// conv merged-launch level decode tables
__device__ const int c_LB[5]   = {0, 1040, 1320, 1416, 1448};
__device__ const int c_NTX[5]  = {10, 5, 3, 2, 1};
__device__ const int c_NTY[5]  = {13, 7, 4, 2, 1};
__device__ const int c_H[5]    = {100, 50, 25, 13, 7};
__device__ const int c_W[5]    = {152, 76, 38, 19, 10};
__device__ const int c_HOFF[5] = {0, 7782400, 9728000, 10214400, 10340864};
// head merged-launch tables
__device__ const int h_HB[5]   = {0, 475, 594, 624, 632};

// ---------------- scratch (static device memory; no allocs) ----------------
__device__ float    g_h[10376704];
__device__ float    g_logit[2 * DFULL];
__device__ float    g_reg[2 * DFULL * 4];
__device__ int      g_topidx[10 * 1000];
__device__ float    g_toplog[10 * 1000];
__device__ float4   g_cbox[NTOT];
__device__ float    g_cscore[NTOT];
__device__ int      g_cvalid[NTOT];
__device__ float    g_csc[NTOT];
__device__ unsigned g_maxbits;

// ---------------- packed fp32x2 helpers (sm_103a FFMA2 path) --------------
typedef unsigned long long u64;

__device__ __forceinline__ u64 pack2(float lo, float hi) {
    u64 r;
    asm("mov.b64 %0, {%1, %2};" : "=l"(r) : "f"(lo), "f"(hi));
    return r;
}
__device__ __forceinline__ u64 fma2(u64 a, u64 b, u64 c) {
    u64 d;
    asm("fma.rn.f32x2 %0, %1, %2, %3;" : "=l"(d) : "l"(a), "l"(b), "l"(c));
    return d;
}
__device__ __forceinline__ void unpack2(float& lo, float& hi, u64 v) {
    asm("mov.b64 {%0, %1}, %2;" : "=f"(lo), "=f"(hi) : "l"(v));
}

// ---------------- conv 3x3 (SAME) + bias + relu, ALL levels in one grid ---
// block: 256 thr = 8 ocGroups x 32 pxGroups; tile 64 oc x (8 rows x 16 cols)
// thread: 8 oc (as 4 packed oc-pairs) x 4 consecutive cols, FFMA2 inner loop
__global__ __launch_bounds__(256, 2)
void conv_kernel(const float* __restrict__ f0, const float* __restrict__ f1,
                 const float* __restrict__ f2, const float* __restrict__ f3,
                 const float* __restrict__ f4,
                 const float* __restrict__ cw, const float* __restrict__ cb) {
    __shared__ float ins[8 * 10 * 20];   // 8 ic x (8+2) rows x stride-20 cols
    __shared__ float wsm[8 * 9 * 64];    // 8 ic x 9 taps x 64 oc

    const int b = blockIdx.x;
    const int lvl = (b < 1040) ? 0 : (b < 1320) ? 1 : (b < 1416) ? 2 : (b < 1448) ? 3 : 4;
    const int r = b - c_LB[lvl];
    const int ntx = c_NTX[lvl];
    const int nt = ntx * c_NTY[lvl];
    const int z = r / nt;
    const int rr = r % nt;
    const int ty = rr / ntx, tx = rr % ntx;
    const int img = z >> 2;
    const int ocBase = (z & 3) * 64;
    const int H = c_H[lvl], W = c_W[lvl];
    const int HWp = H * W;
    const int hoff = c_HOFF[lvl];
    const float* xin =
        ((lvl == 0) ? f0 : (lvl == 1) ? f1 : (lvl == 2) ? f2 : (lvl == 3) ? f3 : f4)
        + (size_t)img * 256 * HWp;

    const int tid = threadIdx.x;
    const int ocg = tid >> 5;          // 0..7 (uniform within warp)
    const int g = tid & 31;
    const int row = g >> 2;            // 0..7
    const int cg = g & 3;              // 0..3 -> cols cg*4 .. cg*4+3
    const int x0 = tx * 16, y0 = ty * 8;

    // acc2[op][p]: oc-pair op (lanes: lo=oc even, hi=oc odd), pixel p
    u64 acc2[4][4];
#pragma unroll
    for (int op = 0; op < 4; op++)
#pragma unroll
        for (int p = 0; p < 4; p++) acc2[op][p] = 0ull;

    for (int ic0 = 0; ic0 < 256; ic0 += 8) {
        __syncthreads();
        // stage input patch: 8 ic x 10 rows x 18 cols (stride 20, zero-pad SAME)
        for (int l = tid; l < 8 * 180; l += 256) {
            int icj = l / 180; int q = l % 180; int py = q / 18; int px = q % 18;
            int gy = y0 - 1 + py, gx = x0 - 1 + px;
            float v = 0.f;
            if (gy >= 0 && gy < H && gx >= 0 && gx < W)
                v = xin[(size_t)(ic0 + icj) * HWp + gy * W + gx];
            ins[(icj * 10 + py) * 20 + px] = v;
        }
        // stage weights: 8 ic x 9 taps x 64 oc
        for (int l = tid; l < 8 * 9 * 64; l += 256) {
            int oci = l / 72; int q = l % 72; int icj = q / 9; int tap = q % 9;
            wsm[(icj * 9 + tap) * 64 + oci] =
                cw[((size_t)(ocBase + oci) * 256 + ic0 + icj) * 9 + tap];
        }
        __syncthreads();

#pragma unroll 1
        for (int ic = 0; ic < 8; ic++) {
            const float* bp = &ins[(ic * 10 + row) * 20 + cg * 4];
#pragma unroll
            for (int ky = 0; ky < 3; ky++) {
                // load 6 input values for this row, pack as (v,v) broadcasts
                float4 v4 = *(const float4*)(bp + ky * 20);
                float2 v2 = *(const float2*)(bp + ky * 20 + 4);
                u64 r2[6];
                r2[0] = pack2(v4.x, v4.x); r2[1] = pack2(v4.y, v4.y);
                r2[2] = pack2(v4.z, v4.z); r2[3] = pack2(v4.w, v4.w);
                r2[4] = pack2(v2.x, v2.x); r2[5] = pack2(v2.y, v2.y);
#pragma unroll
                for (int kx = 0; kx < 3; kx++) {
                    // 8 oc weights = 4 packed pairs, loaded as 2x LDS.128
                    const float* wp = &wsm[(ic * 9 + ky * 3 + kx) * 64 + ocg * 8];
                    ulonglong2 wA = *(const ulonglong2*)wp;        // (w0,w1),(w2,w3)
                    ulonglong2 wB = *(const ulonglong2*)(wp + 4);  // (w4,w5),(w6,w7)
                    u64 wpair[4] = {wA.x, wA.y, wB.x, wB.y};
#pragma unroll
                    for (int op = 0; op < 4; op++)
#pragma unroll
                        for (int p = 0; p < 4; p++)
                            acc2[op][p] = fma2(wpair[op], r2[kx + p], acc2[op][p]);
                }
            }
        }
    }

    // epilogue: unpack + bias + relu + store
    const int gy = y0 + row;
    if (gy < H) {
#pragma unroll
        for (int op = 0; op < 4; op++) {
            int oc0 = ocBase + ocg * 8 + op * 2;
            float b0 = cb[oc0], b1 = cb[oc0 + 1];
            float* dst0 = &g_h[hoff + ((size_t)img * 256 + oc0) * HWp + (size_t)gy * W];
            float* dst1 = dst0 + HWp;
#pragma unroll
            for (int p = 0; p < 4; p++) {
                int gx = x0 + cg * 4 + p;
                if (gx < W) {
                    float lo, hi;
                    unpack2(lo, hi, acc2[op][p]);
                    float v0 = lo + b0, v1 = hi + b1;
                    dst0[gx] = v0 > 0.f ? v0 : 0.f;
                    dst1[gx] = v1 > 0.f ? v1 : 0.f;
                }
            }
        }
    }
}

// ---------------- heads: 15 dot products per pixel, ALL levels one grid ---
__global__ void head_kernel(const float* __restrict__ lw, const float* __restrict__ lb,
                            const float* __restrict__ rw, const float* __restrict__ rb) {
    __shared__ float wsm[15 * 256];
    __shared__ float red[8][32][16];

    const int bx = blockIdx.x;
    const int lvl = (bx < 475) ? 0 : (bx < 594) ? 1 : (bx < 624) ? 2 : (bx < 632) ? 3 : 4;
    const int lb_blk = bx - h_HB[lvl];
    const int HW = d_HW[lvl];
    const int aoff = d_AOFF[lvl];
    const int hoff = c_HOFF[lvl];

    const int tid = threadIdx.x;
    for (int l = tid; l < 15 * 256; l += 256) {
        int o = l >> 8, c = l & 255;
        wsm[l] = (o < 3) ? lw[o * 256 + c] : rw[(o - 3) * 256 + c];
    }
    __syncthreads();

    const int img = blockIdx.y;
    const int pix = lb_blk * 32 + (tid & 31);
    const int cg = tid >> 5;

    float acc[15];
#pragma unroll
    for (int o = 0; o < 15; o++) acc[o] = 0.f;

    if (pix < HW) {
        const float* hp = g_h + hoff + ((size_t)img * 256 + cg * 32) * HW + pix;
#pragma unroll 4
        for (int j = 0; j < 32; j++) {
            float v = hp[(size_t)j * HW];
            int c = cg * 32 + j;
#pragma unroll
            for (int o = 0; o < 15; o++) acc[o] += v * wsm[o * 256 + c];
        }
    }
#pragma unroll
    for (int o = 0; o < 15; o++) red[cg][tid & 31][o] = acc[o];
    __syncthreads();

    for (int l = tid; l < 32 * 15; l += 256) {
        int px = l / 15, o = l % 15;
        float s = 0.f;
#pragma unroll
        for (int g = 0; g < 8; g++) s += red[g][px][o];
        int p = lb_blk * 32 + px;
        if (p < HW) {
            if (o < 3) {
                g_logit[(size_t)img * DFULL + aoff + p * 3 + o] = s + lb[o];
            } else {
                int rr = o - 3, a = rr >> 2, comp = rr & 3;
                g_reg[((size_t)img * DFULL + aoff + p * 3 + a) * 4 + comp] = s + rb[rr];
            }
        }
    }
}

// ---------------- exact top-k (set + lowest-index ties) radix select ------
__device__ __forceinline__ unsigned fkey(float f) {
    unsigned u = __float_as_uint(f);
    return (u & 0x80000000u) ? ~u : (u | 0x80000000u);
}

__global__ void topk_kernel() {
    const int b = blockIdx.x;
    const int im = b / 5, lvl = b % 5;
    const int L = 3 * d_HW[lvl];
    const int K = d_K[lvl];
    const float* src = g_logit + (size_t)im * DFULL + d_AOFF[lvl];
    int* oidx = g_topidx + b * 1000;
    float* olog = g_toplog + b * 1000;
    const int tid = threadIdx.x;
    const int nth = blockDim.x;

    if (L <= K) {
        for (int i = tid; i < L; i += nth) { oidx[i] = i; olog[i] = src[i]; }
        return;
    }

    __shared__ unsigned hist[2048];
    __shared__ unsigned sfxA[2048];
    __shared__ unsigned sfxB[2048];
    __shared__ int eqlist[1024];
    __shared__ int sh_d, sh_sub, sh_cnt, sh_eq;

    unsigned prefix = 0;
    int bitsdone = 0;
    int krem = K;
    const int widths[3] = {11, 11, 10};

    for (int pass = 0; pass < 3; pass++) {
        int wb = widths[pass];
        int nb = 1 << wb;
        int shift = 32 - bitsdone - wb;
        for (int l = tid; l < nb; l += nth) hist[l] = 0;
        __syncthreads();
        for (int i = tid; i < L; i += nth) {
            unsigned u = fkey(src[i]);
            if (bitsdone == 0 || (u >> (32 - bitsdone)) == prefix)
                atomicAdd(&hist[(u >> shift) & (nb - 1)], 1u);
        }
        __syncthreads();
        unsigned* s = sfxA; unsigned* d = sfxB;
        for (int l = tid; l < nb; l += nth) s[l] = hist[l];
        for (int off = 1; off < nb; off <<= 1) {
            __syncthreads();
            for (int l = tid; l < nb; l += nth)
                d[l] = s[l] + ((l + off < nb) ? s[l + off] : 0u);
            unsigned* t = s; s = d; d = t;
        }
        __syncthreads();
        for (int l = tid; l < nb; l += nth) {
            unsigned ge = s[l];
            unsigned gt = (l + 1 < nb) ? s[l + 1] : 0u;
            if ((int)ge >= krem && (int)gt < krem) { sh_d = l; sh_sub = (int)gt; }
        }
        __syncthreads();
        prefix = (prefix << wb) | (unsigned)sh_d;
        krem -= sh_sub;
        bitsdone += wb;
        __syncthreads();
    }

    const unsigned T = prefix;
    if (tid == 0) { sh_cnt = 0; sh_eq = 0; }
    __syncthreads();

    for (int i = tid; i < L; i += nth) {
        if (fkey(src[i]) == T) {
            int p = atomicAdd(&sh_eq, 1);
            if (p < 1024) eqlist[p] = i;
        }
    }
    __syncthreads();
    int m = sh_eq < 1024 ? sh_eq : 1024;
    for (int l = tid; l < 1024; l += nth)
        if (l >= m) eqlist[l] = 0x7FFFFFFF;
    __syncthreads();
    for (int k = 2; k <= 1024; k <<= 1) {
        for (int j = k >> 1; j > 0; j >>= 1) {
            if (tid < 1024) {
                int ixj = tid ^ j;
                if (ixj > tid) {
                    int a = eqlist[tid], bb = eqlist[ixj];
                    bool asc = ((tid & k) == 0);
                    if (asc ? (a > bb) : (a < bb)) { eqlist[tid] = bb; eqlist[ixj] = a; }
                }
            }
            __syncthreads();
        }
    }

    for (int i = tid; i < L; i += nth) {
        float f = src[i];
        if (fkey(f) > T) {
            int p = atomicAdd(&sh_cnt, 1);
            oidx[p] = i; olog[p] = f;
        }
    }
    __syncthreads();
    for (int l = tid; l < krem; l += nth) {
        int i = eqlist[l];
        int p = atomicAdd(&sh_cnt, 1);
        oidx[p] = i; olog[p] = src[i];
    }
}

// ---- sort each group's selection by (logit desc, index asc) --------------
__global__ void sortsel_kernel() {
    __shared__ float skey[1024];
    __shared__ int sidx[1024];
    const int b = blockIdx.x;
    const int K = d_K[b % 5];
    const int tid = threadIdx.x;

    float k = -FLT_MAX; int ix = 0x7FFFFFFF;
    if (tid < K) { k = g_toplog[b * 1000 + tid]; ix = g_topidx[b * 1000 + tid]; }
    skey[tid] = k; sidx[tid] = ix;
    __syncthreads();

    for (int kk = 2; kk <= 1024; kk <<= 1) {
        for (int j = kk >> 1; j > 0; j >>= 1) {
            int ixj = tid ^ j;
            if (ixj > tid) {
                float ka = skey[tid], kb = skey[ixj];
                int ia = sidx[tid], ib = sidx[ixj];
                bool aGb = (ka > kb) || (ka == kb && ia < ib);
                bool desc = ((tid & kk) == 0);
                if (desc ? !aGb : aGb) {
                    skey[tid] = kb; skey[ixj] = ka;
                    sidx[tid] = ib; sidx[ixj] = ia;
                }
            }
            __syncthreads();
        }
    }
    if (tid < K) { g_toplog[b * 1000 + tid] = skey[tid]; g_topidx[b * 1000 + tid] = sidx[tid]; }
}

// ---------------- decode + clip + validity + sigmoid + global max --------
__global__ void maxinit_kernel() { g_maxbits = 0u; }

__global__ void decode_kernel(const float* __restrict__ p0, const float* __restrict__ p1,
                              const float* __restrict__ p2, const float* __restrict__ p3,
                              const float* __restrict__ p4, const float* __restrict__ imsz) {
    int q = blockIdx.x * blockDim.x + threadIdx.x;
    if (q >= NTOT) return;
    int im = q / DSEL;
    int r = q % DSEL;
    int lvl = (r < 1000) ? 0 : (r < 2000) ? 1 : (r < 3000) ? 2 : (r < 3741) ? 3 : 4;
    int slot = r - d_COFF[lvl];
    int g = (im * 5 + lvl) * 1000 + slot;
    int idx = g_topidx[g];
    float logit = g_toplog[g];

    const float* pri =
        ((lvl == 0) ? p0 : (lvl == 1) ? p1 : (lvl == 2) ? p2 : (lvl == 3) ? p3 : p4) +
        (size_t)idx * 4;
    size_t rb = ((size_t)im * DFULL + d_AOFF[lvl] + idx) * 4;

    float dx = g_reg[rb + 0], dy = g_reg[rb + 1];
    float dw = fminf(g_reg[rb + 2], LOG_MAXF);
    float dh = fminf(g_reg[rb + 3], LOG_MAXF);
    float pcx = pri[0], pcy = pri[1], pw = pri[2], ph = pri[3];
    float cx = dx * pw + pcx, cy = dy * ph + pcy;
    float w = pw * expf(dw), h = ph * expf(dh);
    float x1 = cx - 0.5f * w, y1 = cy - 0.5f * h;
    float x2 = cx + 0.5f * w, y2 = cy + 0.5f * h;
    float Wc = imsz[im * 2 + 1], Hc = imsz[im * 2 + 0];
    x1 = fminf(fmaxf(x1, 0.f), Wc); x2 = fminf(fmaxf(x2, 0.f), Wc);
    y1 = fminf(fmaxf(y1, 0.f), Hc); y2 = fminf(fmaxf(y2, 0.f), Hc);

    g_cbox[q] = make_float4(x1, y1, x2, y2);
    g_cscore[q] = 1.f / (1.f + expf(-logit));
    g_cvalid[q] = ((x2 - x1) >= 0.001f) && ((y2 - y1) >= 0.001f);
    g_csc[q] = -1.0f;

    float m4 = fmaxf(fmaxf(x1, y1), fmaxf(x2, y2));
    atomicMax(&g_maxbits, __float_as_uint(m4));
}

// ---------------- per-group NMS: stable sort + bit-exact shifted IoU ------
__global__ void nms_kernel() {
    __shared__ float skey[1024];
    __shared__ int sidx[1024];
    __shared__ float4 sbox[1024];
    __shared__ float sarea[1024];
    __shared__ unsigned char srem[1024];

    const int b = blockIdx.x;
    const int im = b / 5, lvl = b % 5;
    const int base = im * DSEL + d_COFF[lvl];
    const int cnt = d_K[lvl];
    const int tid = threadIdx.x;

    float sc = -FLT_MAX;
    if (tid < cnt && g_cvalid[base + tid]) sc = g_cscore[base + tid];
    skey[tid] = sc;
    sidx[tid] = tid;

    for (int k = 2; k <= 1024; k <<= 1) {
        for (int j = k >> 1; j > 0; j >>= 1) {
            __syncthreads();
            int ixj = tid ^ j;
            if (ixj > tid) {
                float ka = skey[tid], kb = skey[ixj];
                int ia = sidx[tid], ib = sidx[ixj];
                bool aGb = (ka > kb) || (ka == kb && ia < ib);
                bool desc = ((tid & k) == 0);
                if (desc ? !aGb : aGb) {
                    skey[tid] = kb; skey[ixj] = ka;
                    sidx[tid] = ib; sidx[ixj] = ia;
                }
            }
        }
    }
    __syncthreads();

    {
        float M = __uint_as_float(g_maxbits);
        float off = __fmul_rn((float)(im * 10 + lvl), __fadd_rn(M, 1.0f));
        if (skey[tid] > -1e37f) {
            float4 bx = g_cbox[base + sidx[tid]];
            float sx1 = __fadd_rn(bx.x, off), sy1 = __fadd_rn(bx.y, off);
            float sx2 = __fadd_rn(bx.z, off), sy2 = __fadd_rn(bx.w, off);
            sbox[tid] = make_float4(sx1, sy1, sx2, sy2);
            sarea[tid] = __fmul_rn(__fsub_rn(sx2, sx1), __fsub_rn(sy2, sy1));
        } else {
            sbox[tid] = make_float4(0.f, 0.f, 0.f, 0.f);
            sarea[tid] = 0.f;
        }
        srem[tid] = 0;
    }
    __syncthreads();

    for (int i = 0; i < cnt; i++) {
        if (skey[i] <= -1e37f) break;
        bool alive = (srem[i] == 0);
        if (alive && tid > i && srem[tid] == 0 && skey[tid] > -1e37f) {
            float4 A = sbox[i], B = sbox[tid];
            float lx = fmaxf(A.x, B.x), ly = fmaxf(A.y, B.y);
            float rx = fminf(A.z, B.z), ry = fminf(A.w, B.w);
            float w = fmaxf(__fsub_rn(rx, lx), 0.f);
            float h = fmaxf(__fsub_rn(ry, ly), 0.f);
            float inter = __fmul_rn(w, h);
            float denom = __fadd_rn(__fsub_rn(__fadd_rn(sarea[i], sarea[tid]), inter), 1e-9f);
            float iou = __fdiv_rn(inter, denom);
            if (iou > 0.7f) srem[tid] = 1;
        }
        __syncthreads();
    }

    if (skey[tid] > -1e37f && srem[tid] == 0 && sidx[tid] < cnt) {
        g_csc[base + sidx[tid]] = skey[tid];
    }
}

// ---------------- final: per-image stable sort, emit top-1000 -------------
__global__ void final_kernel(float* __restrict__ out) {
    __shared__ float skey[4096];
    __shared__ int sidx[4096];
    const int im = blockIdx.x;
    const int tid = threadIdx.x;

    for (int e = 0; e < 4; e++) {
        int i = tid + e * 1024;
        float v = -3.0f;
        if (i < DSEL) v = g_csc[im * DSEL + i];
        skey[i] = v;
        sidx[i] = i;
    }
    __syncthreads();

    for (int k = 2; k <= 4096; k <<= 1) {
        for (int j = k >> 1; j > 0; j >>= 1) {
            for (int e = 0; e < 4; e++) {
                int i = tid + e * 1024;
                int ixj = i ^ j;
                if (ixj > i) {
                    float ka = skey[i], kb = skey[ixj];
                    int ia = sidx[i], ib = sidx[ixj];
                    bool aGb = (ka > kb) || (ka == kb && ia < ib);
                    bool desc = ((i & k) == 0);
                    if (desc ? !aGb : aGb) {
                        skey[i] = kb; skey[ixj] = ka;
                        sidx[i] = ib; sidx[ixj] = ia;
                    }
                }
            }
            __syncthreads();
        }
    }

    if (tid < 1000) {
        float v = skey[tid];
        float* o = out + ((size_t)im * 1000 + tid) * 5;
        if (v > -0.5f) {
            float4 bx = g_cbox[im * DSEL + sidx[tid]];
            o[0] = bx.x; o[1] = bx.y; o[2] = bx.z; o[3] = bx.w; o[4] = v;
        } else {
            o[0] = 0.f; o[1] = 0.f; o[2] = 0.f; o[3] = 0.f; o[4] = 0.f;
        }
    }
}

// ---------------- launch ---------------------------------------------------
extern "C" void kernel_launch(void* const* d_in, const int* in_sizes, int n_in,
                              void* d_out, int out_size) {
    const float *fm[5] = {0, 0, 0, 0, 0}, *pr[5] = {0, 0, 0, 0, 0};
    const float *imsz = 0, *cw = 0, *cb = 0, *lw = 0, *lb = 0, *rw = 0, *rbv = 0;
    for (int i = 0; i < n_in; i++) {
        const float* p = (const float*)d_in[i];
        switch (in_sizes[i]) {
            case 7782400: fm[0] = p; break;
            case 1945600: fm[1] = p; break;
            case 486400:  fm[2] = p; break;
            case 126464:  fm[3] = p; break;
            case 35840:   fm[4] = p; break;
            case 182400:  pr[0] = p; break;
            case 45600:   pr[1] = p; break;
            case 11400:   pr[2] = p; break;
            case 2964:    pr[3] = p; break;
            case 840:     pr[4] = p; break;
            case 4:       imsz = p; break;
            case 589824:  cw = p; break;
            case 256:     cb = p; break;
            case 768:     lw = p; break;
            case 3:       lb = p; break;
            case 3072:    rw = p; break;
            case 12:      rbv = p; break;
            default: break;
        }
    }

    conv_kernel<<<1456, 256>>>(fm[0], fm[1], fm[2], fm[3], fm[4], cw, cb);
    head_kernel<<<dim3(635, 2), 256>>>(lw, lb, rw, rbv);
    topk_kernel<<<10, 1024>>>();
    sortsel_kernel<<<10, 1024>>>();
    maxinit_kernel<<<1, 1>>>();
    decode_kernel<<<(NTOT + 255) / 256, 256>>>(pr[0], pr[1], pr[2], pr[3], pr[4], imsz);
    nms_kernel<<<10, 1024>>>();
    final_kernel<<<2, 1024>>>((float*)d_out);
}

// round 9
// speedup vs baseline: 1.7329x; 1.2508x over previous
#include <cuda_runtime.h>
#include <math.h>
#include <float.h>

// ---------------- problem constants (fixed by setup_inputs) ----------------
#define DFULL 60801
#define DSEL  3951
#define NTOT  7902
#define LOG_MAXF 4.135166556742356f

__device__ const int d_HW[5]   = {15200, 3800, 950, 247, 70};
__device__ const int d_K[5]    = {1000, 1000, 1000, 741, 210};
__device__ const int d_AOFF[5] = {0, 45600, 57000, 59850, 60591};
__device__ const int d_COFF[5] = {0, 1000, 2000, 3000, 3741};

// conv merged-launch level decode tables
__device__ const int c_LB[5]   = {0, 1040, 1320, 1416, 1448};
__device__ const int c_NTX[5]  = {10, 5, 3, 2, 1};
__device__ const int c_NTY[5]  = {13, 7, 4, 2, 1};
__device__ const int c_H[5]    = {100, 50, 25, 13, 7};
__device__ const int c_W[5]    = {152, 76, 38, 19, 10};
__device__ const int c_HOFF[5] = {0, 7782400, 9728000, 10214400, 10340864};
// head merged-launch tables
__device__ const int h_HB[5]   = {0, 475, 594, 624, 632};

// ---------------- scratch (static device memory; no allocs) ----------------
__device__ float    g_h[10376704];
__device__ float    g_cwT[589824];        // weights transposed: [ic][tap][oc]
__device__ float    g_logit[2 * DFULL];
__device__ float    g_reg[2 * DFULL * 4];
__device__ int      g_topidx[10 * 1000];
__device__ float    g_toplog[10 * 1000];
__device__ float4   g_cbox[NTOT];
__device__ float    g_cscore[NTOT];
__device__ int      g_cvalid[NTOT];
__device__ float    g_csc[NTOT];
__device__ unsigned g_maxbits;

// ---------------- packed fp32x2 helpers (sm_103a FFMA2 path) --------------
typedef unsigned long long u64;

__device__ __forceinline__ u64 pack2(float lo, float hi) {
    u64 r;
    asm("mov.b64 %0, {%1, %2};" : "=l"(r) : "f"(lo), "f"(hi));
    return r;
}
__device__ __forceinline__ u64 fma2(u64 a, u64 b, u64 c) {
    u64 d;
    asm("fma.rn.f32x2 %0, %1, %2, %3;" : "=l"(d) : "l"(a), "l"(b), "l"(c));
    return d;
}
__device__ __forceinline__ void unpack2(float& lo, float& hi, u64 v) {
    asm("mov.b64 {%0, %1}, %2;" : "=f"(lo), "=f"(hi) : "l"(v));
}

// ---------------- weight transpose: cw[oc][ic][tap] -> cwT[ic][tap][oc] ----
// one-time, tiny; makes conv weight staging fully coalesced (8x less traffic)
__global__ void wtrans_kernel(const float* __restrict__ cw) {
    int l = blockIdx.x * blockDim.x + threadIdx.x;   // out index, oc fastest
    if (l >= 589824) return;
    int oc = l & 255;
    int q = l >> 8;          // ic*9 + tap
    int tap = q % 9;
    int ic = q / 9;
    g_cwT[l] = cw[((size_t)oc * 256 + ic) * 9 + tap];
}

// ---------------- conv 3x3 (SAME) + bias + relu, ALL levels in one grid ---
// block: 256 thr = 8 ocGroups x 32 pxGroups; tile 64 oc x (8 rows x 16 cols)
// thread: 8 oc (as 4 packed oc-pairs) x 4 consecutive cols, FFMA2 inner loop
__global__ __launch_bounds__(256, 2)
void conv_kernel(const float* __restrict__ f0, const float* __restrict__ f1,
                 const float* __restrict__ f2, const float* __restrict__ f3,
                 const float* __restrict__ f4,
                 const float* __restrict__ cb) {
    __shared__ float ins[8 * 10 * 20];   // 8 ic x (8+2) rows x stride-20 cols
    __shared__ float wsm[8 * 9 * 64];    // 8 ic x 9 taps x 64 oc

    const int b = blockIdx.x;
    const int lvl = (b < 1040) ? 0 : (b < 1320) ? 1 : (b < 1416) ? 2 : (b < 1448) ? 3 : 4;
    const int r = b - c_LB[lvl];
    const int ntx = c_NTX[lvl];
    const int nt = ntx * c_NTY[lvl];
    const int z = r / nt;
    const int rr = r % nt;
    const int ty = rr / ntx, tx = rr % ntx;
    const int img = z >> 2;
    const int ocBase = (z & 3) * 64;
    const int H = c_H[lvl], W = c_W[lvl];
    const int HWp = H * W;
    const int hoff = c_HOFF[lvl];
    const float* xin =
        ((lvl == 0) ? f0 : (lvl == 1) ? f1 : (lvl == 2) ? f2 : (lvl == 3) ? f3 : f4)
        + (size_t)img * 256 * HWp;

    const int tid = threadIdx.x;
    const int ocg = tid >> 5;          // 0..7 (uniform within warp)
    const int g = tid & 31;
    const int row = g >> 2;            // 0..7
    const int cg = g & 3;              // 0..3 -> cols cg*4 .. cg*4+3
    const int x0 = tx * 16, y0 = ty * 8;

    // acc2[op][p]: oc-pair op (lanes: lo=oc even, hi=oc odd), pixel p
    u64 acc2[4][4];
#pragma unroll
    for (int op = 0; op < 4; op++)
#pragma unroll
        for (int p = 0; p < 4; p++) acc2[op][p] = 0ull;

    for (int ic0 = 0; ic0 < 256; ic0 += 8) {
        __syncthreads();
        // stage input patch: 8 ic x 10 rows x 18 cols (stride 20, zero-pad SAME)
        for (int l = tid; l < 8 * 180; l += 256) {
            int icj = l / 180; int q = l % 180; int py = q / 18; int px = q % 18;
            int gy = y0 - 1 + py, gx = x0 - 1 + px;
            float v = 0.f;
            if (gy >= 0 && gy < H && gx >= 0 && gx < W)
                v = xin[(size_t)(ic0 + icj) * HWp + gy * W + gx];
            ins[(icj * 10 + py) * 20 + px] = v;
        }
        // stage weights from transposed layout: FULLY COALESCED.
        // wsm layout (icj*9+tap)*64+oci maps directly onto cwT rows.
        {
            const float* src = &g_cwT[((size_t)ic0 * 9) * 256 + ocBase];
            // l enumerates (icj,tap) pairs x 64 oc: consecutive l -> consecutive oci
#pragma unroll
            for (int it = 0; it < 18; it++) {
                int l = tid + it * 256;          // 0..4607
                int pair = l >> 6;               // icj*9+tap
                int oci = l & 63;
                wsm[l] = src[(size_t)pair * 256 + oci];
            }
        }
        __syncthreads();

#pragma unroll 1
        for (int ic = 0; ic < 8; ic++) {
            const float* bp = &ins[(ic * 10 + row) * 20 + cg * 4];
#pragma unroll
            for (int ky = 0; ky < 3; ky++) {
                // load 6 input values for this row, pack as (v,v) broadcasts
                float4 v4 = *(const float4*)(bp + ky * 20);
                float2 v2 = *(const float2*)(bp + ky * 20 + 4);
                u64 r2[6];
                r2[0] = pack2(v4.x, v4.x); r2[1] = pack2(v4.y, v4.y);
                r2[2] = pack2(v4.z, v4.z); r2[3] = pack2(v4.w, v4.w);
                r2[4] = pack2(v2.x, v2.x); r2[5] = pack2(v2.y, v2.y);
#pragma unroll
                for (int kx = 0; kx < 3; kx++) {
                    // 8 oc weights = 4 packed pairs, loaded as 2x LDS.128
                    const float* wp = &wsm[(ic * 9 + ky * 3 + kx) * 64 + ocg * 8];
                    ulonglong2 wA = *(const ulonglong2*)wp;        // (w0,w1),(w2,w3)
                    ulonglong2 wB = *(const ulonglong2*)(wp + 4);  // (w4,w5),(w6,w7)
                    u64 wpair[4] = {wA.x, wA.y, wB.x, wB.y};
#pragma unroll
                    for (int op = 0; op < 4; op++)
#pragma unroll
                        for (int p = 0; p < 4; p++)
                            acc2[op][p] = fma2(wpair[op], r2[kx + p], acc2[op][p]);
                }
            }
        }
    }

    // epilogue: unpack + bias + relu + store
    const int gy = y0 + row;
    if (gy < H) {
#pragma unroll
        for (int op = 0; op < 4; op++) {
            int oc0 = ocBase + ocg * 8 + op * 2;
            float b0 = cb[oc0], b1 = cb[oc0 + 1];
            float* dst0 = &g_h[hoff + ((size_t)img * 256 + oc0) * HWp + (size_t)gy * W];
            float* dst1 = dst0 + HWp;
#pragma unroll
            for (int p = 0; p < 4; p++) {
                int gx = x0 + cg * 4 + p;
                if (gx < W) {
                    float lo, hi;
                    unpack2(lo, hi, acc2[op][p]);
                    float v0 = lo + b0, v1 = hi + b1;
                    dst0[gx] = v0 > 0.f ? v0 : 0.f;
                    dst1[gx] = v1 > 0.f ? v1 : 0.f;
                }
            }
        }
    }
}

// ---------------- heads: 15 dot products per pixel, ALL levels one grid ---
__global__ void head_kernel(const float* __restrict__ lw, const float* __restrict__ lb,
                            const float* __restrict__ rw, const float* __restrict__ rb) {
    __shared__ float wsm[15 * 256];
    __shared__ float red[8][32][16];

    const int bx = blockIdx.x;
    const int lvl = (bx < 475) ? 0 : (bx < 594) ? 1 : (bx < 624) ? 2 : (bx < 632) ? 3 : 4;
    const int lb_blk = bx - h_HB[lvl];
    const int HW = d_HW[lvl];
    const int aoff = d_AOFF[lvl];
    const int hoff = c_HOFF[lvl];

    const int tid = threadIdx.x;
    for (int l = tid; l < 15 * 256; l += 256) {
        int o = l >> 8, c = l & 255;
        wsm[l] = (o < 3) ? lw[o * 256 + c] : rw[(o - 3) * 256 + c];
    }
    __syncthreads();

    const int img = blockIdx.y;
    const int pix = lb_blk * 32 + (tid & 31);
    const int cg = tid >> 5;

    float acc[15];
#pragma unroll
    for (int o = 0; o < 15; o++) acc[o] = 0.f;

    if (pix < HW) {
        const float* hp = g_h + hoff + ((size_t)img * 256 + cg * 32) * HW + pix;
#pragma unroll 4
        for (int j = 0; j < 32; j++) {
            float v = hp[(size_t)j * HW];
            int c = cg * 32 + j;
#pragma unroll
            for (int o = 0; o < 15; o++) acc[o] += v * wsm[o * 256 + c];
        }
    }
#pragma unroll
    for (int o = 0; o < 15; o++) red[cg][tid & 31][o] = acc[o];
    __syncthreads();

    for (int l = tid; l < 32 * 15; l += 256) {
        int px = l / 15, o = l % 15;
        float s = 0.f;
#pragma unroll
        for (int g = 0; g < 8; g++) s += red[g][px][o];
        int p = lb_blk * 32 + px;
        if (p < HW) {
            if (o < 3) {
                g_logit[(size_t)img * DFULL + aoff + p * 3 + o] = s + lb[o];
            } else {
                int rr = o - 3, a = rr >> 2, comp = rr & 3;
                g_reg[((size_t)img * DFULL + aoff + p * 3 + a) * 4 + comp] = s + rb[rr];
            }
        }
    }
}

// ---------------- exact top-k (set + lowest-index ties) radix select ------
__device__ __forceinline__ unsigned fkey(float f) {
    unsigned u = __float_as_uint(f);
    return (u & 0x80000000u) ? ~u : (u | 0x80000000u);
}

__global__ void topk_kernel() {
    const int b = blockIdx.x;
    const int im = b / 5, lvl = b % 5;
    const int L = 3 * d_HW[lvl];
    const int K = d_K[lvl];
    const float* src = g_logit + (size_t)im * DFULL + d_AOFF[lvl];
    int* oidx = g_topidx + b * 1000;
    float* olog = g_toplog + b * 1000;
    const int tid = threadIdx.x;
    const int nth = blockDim.x;

    if (L <= K) {
        for (int i = tid; i < L; i += nth) { oidx[i] = i; olog[i] = src[i]; }
        return;
    }

    __shared__ unsigned hist[2048];
    __shared__ unsigned sfxA[2048];
    __shared__ unsigned sfxB[2048];
    __shared__ int eqlist[1024];
    __shared__ int sh_d, sh_sub, sh_cnt, sh_eq;

    unsigned prefix = 0;
    int bitsdone = 0;
    int krem = K;
    const int widths[3] = {11, 11, 10};

    for (int pass = 0; pass < 3; pass++) {
        int wb = widths[pass];
        int nb = 1 << wb;
        int shift = 32 - bitsdone - wb;
        for (int l = tid; l < nb; l += nth) hist[l] = 0;
        __syncthreads();
        for (int i = tid; i < L; i += nth) {
            unsigned u = fkey(src[i]);
            if (bitsdone == 0 || (u >> (32 - bitsdone)) == prefix)
                atomicAdd(&hist[(u >> shift) & (nb - 1)], 1u);
        }
        __syncthreads();
        unsigned* s = sfxA; unsigned* d = sfxB;
        for (int l = tid; l < nb; l += nth) s[l] = hist[l];
        for (int off = 1; off < nb; off <<= 1) {
            __syncthreads();
            for (int l = tid; l < nb; l += nth)
                d[l] = s[l] + ((l + off < nb) ? s[l + off] : 0u);
            unsigned* t = s; s = d; d = t;
        }
        __syncthreads();
        for (int l = tid; l < nb; l += nth) {
            unsigned ge = s[l];
            unsigned gt = (l + 1 < nb) ? s[l + 1] : 0u;
            if ((int)ge >= krem && (int)gt < krem) { sh_d = l; sh_sub = (int)gt; }
        }
        __syncthreads();
        prefix = (prefix << wb) | (unsigned)sh_d;
        krem -= sh_sub;
        bitsdone += wb;
        __syncthreads();
    }

    const unsigned T = prefix;
    if (tid == 0) { sh_cnt = 0; sh_eq = 0; }
    __syncthreads();

    for (int i = tid; i < L; i += nth) {
        if (fkey(src[i]) == T) {
            int p = atomicAdd(&sh_eq, 1);
            if (p < 1024) eqlist[p] = i;
        }
    }
    __syncthreads();
    int m = sh_eq < 1024 ? sh_eq : 1024;
    for (int l = tid; l < 1024; l += nth)
        if (l >= m) eqlist[l] = 0x7FFFFFFF;
    __syncthreads();
    for (int k = 2; k <= 1024; k <<= 1) {
        for (int j = k >> 1; j > 0; j >>= 1) {
            if (tid < 1024) {
                int ixj = tid ^ j;
                if (ixj > tid) {
                    int a = eqlist[tid], bb = eqlist[ixj];
                    bool asc = ((tid & k) == 0);
                    if (asc ? (a > bb) : (a < bb)) { eqlist[tid] = bb; eqlist[ixj] = a; }
                }
            }
            __syncthreads();
        }
    }

    for (int i = tid; i < L; i += nth) {
        float f = src[i];
        if (fkey(f) > T) {
            int p = atomicAdd(&sh_cnt, 1);
            oidx[p] = i; olog[p] = f;
        }
    }
    __syncthreads();
    for (int l = tid; l < krem; l += nth) {
        int i = eqlist[l];
        int p = atomicAdd(&sh_cnt, 1);
        oidx[p] = i; olog[p] = src[i];
    }
}

// ---- sort each group's selection by (logit desc, index asc) --------------
__global__ void sortsel_kernel() {
    __shared__ float skey[1024];
    __shared__ int sidx[1024];
    const int b = blockIdx.x;
    const int K = d_K[b % 5];
    const int tid = threadIdx.x;

    float k = -FLT_MAX; int ix = 0x7FFFFFFF;
    if (tid < K) { k = g_toplog[b * 1000 + tid]; ix = g_topidx[b * 1000 + tid]; }
    skey[tid] = k; sidx[tid] = ix;
    __syncthreads();

    for (int kk = 2; kk <= 1024; kk <<= 1) {
        for (int j = kk >> 1; j > 0; j >>= 1) {
            int ixj = tid ^ j;
            if (ixj > tid) {
                float ka = skey[tid], kb = skey[ixj];
                int ia = sidx[tid], ib = sidx[ixj];
                bool aGb = (ka > kb) || (ka == kb && ia < ib);
                bool desc = ((tid & kk) == 0);
                if (desc ? !aGb : aGb) {
                    skey[tid] = kb; skey[ixj] = ka;
                    sidx[tid] = ib; sidx[ixj] = ia;
                }
            }
            __syncthreads();
        }
    }
    if (tid < K) { g_toplog[b * 1000 + tid] = skey[tid]; g_topidx[b * 1000 + tid] = sidx[tid]; }
}

// ---------------- decode + clip + validity + sigmoid + global max --------
__global__ void maxinit_kernel() { g_maxbits = 0u; }

__global__ void decode_kernel(const float* __restrict__ p0, const float* __restrict__ p1,
                              const float* __restrict__ p2, const float* __restrict__ p3,
                              const float* __restrict__ p4, const float* __restrict__ imsz) {
    int q = blockIdx.x * blockDim.x + threadIdx.x;
    if (q >= NTOT) return;
    int im = q / DSEL;
    int r = q % DSEL;
    int lvl = (r < 1000) ? 0 : (r < 2000) ? 1 : (r < 3000) ? 2 : (r < 3741) ? 3 : 4;
    int slot = r - d_COFF[lvl];
    int g = (im * 5 + lvl) * 1000 + slot;
    int idx = g_topidx[g];
    float logit = g_toplog[g];

    const float* pri =
        ((lvl == 0) ? p0 : (lvl == 1) ? p1 : (lvl == 2) ? p2 : (lvl == 3) ? p3 : p4) +
        (size_t)idx * 4;
    size_t rb = ((size_t)im * DFULL + d_AOFF[lvl] + idx) * 4;

    float dx = g_reg[rb + 0], dy = g_reg[rb + 1];
    float dw = fminf(g_reg[rb + 2], LOG_MAXF);
    float dh = fminf(g_reg[rb + 3], LOG_MAXF);
    float pcx = pri[0], pcy = pri[1], pw = pri[2], ph = pri[3];
    float cx = dx * pw + pcx, cy = dy * ph + pcy;
    float w = pw * expf(dw), h = ph * expf(dh);
    float x1 = cx - 0.5f * w, y1 = cy - 0.5f * h;
    float x2 = cx + 0.5f * w, y2 = cy + 0.5f * h;
    float Wc = imsz[im * 2 + 1], Hc = imsz[im * 2 + 0];
    x1 = fminf(fmaxf(x1, 0.f), Wc); x2 = fminf(fmaxf(x2, 0.f), Wc);
    y1 = fminf(fmaxf(y1, 0.f), Hc); y2 = fminf(fmaxf(y2, 0.f), Hc);

    g_cbox[q] = make_float4(x1, y1, x2, y2);
    g_cscore[q] = 1.f / (1.f + expf(-logit));
    g_cvalid[q] = ((x2 - x1) >= 0.001f) && ((y2 - y1) >= 0.001f);
    g_csc[q] = -1.0f;

    float m4 = fmaxf(fmaxf(x1, y1), fmaxf(x2, y2));
    atomicMax(&g_maxbits, __float_as_uint(m4));
}

// ---------------- per-group NMS: stable sort + bit-exact shifted IoU ------
__global__ void nms_kernel() {
    __shared__ float skey[1024];
    __shared__ int sidx[1024];
    __shared__ float4 sbox[1024];
    __shared__ float sarea[1024];
    __shared__ unsigned char srem[1024];

    const int b = blockIdx.x;
    const int im = b / 5, lvl = b % 5;
    const int base = im * DSEL + d_COFF[lvl];
    const int cnt = d_K[lvl];
    const int tid = threadIdx.x;

    float sc = -FLT_MAX;
    if (tid < cnt && g_cvalid[base + tid]) sc = g_cscore[base + tid];
    skey[tid] = sc;
    sidx[tid] = tid;

    for (int k = 2; k <= 1024; k <<= 1) {
        for (int j = k >> 1; j > 0; j >>= 1) {
            __syncthreads();
            int ixj = tid ^ j;
            if (ixj > tid) {
                float ka = skey[tid], kb = skey[ixj];
                int ia = sidx[tid], ib = sidx[ixj];
                bool aGb = (ka > kb) || (ka == kb && ia < ib);
                bool desc = ((tid & k) == 0);
                if (desc ? !aGb : aGb) {
                    skey[tid] = kb; skey[ixj] = ka;
                    sidx[tid] = ib; sidx[ixj] = ia;
                }
            }
        }
    }
    __syncthreads();

    {
        float M = __uint_as_float(g_maxbits);
        float off = __fmul_rn((float)(im * 10 + lvl), __fadd_rn(M, 1.0f));
        if (skey[tid] > -1e37f) {
            float4 bx = g_cbox[base + sidx[tid]];
            float sx1 = __fadd_rn(bx.x, off), sy1 = __fadd_rn(bx.y, off);
            float sx2 = __fadd_rn(bx.z, off), sy2 = __fadd_rn(bx.w, off);
            sbox[tid] = make_float4(sx1, sy1, sx2, sy2);
            sarea[tid] = __fmul_rn(__fsub_rn(sx2, sx1), __fsub_rn(sy2, sy1));
        } else {
            sbox[tid] = make_float4(0.f, 0.f, 0.f, 0.f);
            sarea[tid] = 0.f;
        }
        srem[tid] = 0;
    }
    __syncthreads();

    for (int i = 0; i < cnt; i++) {
        if (skey[i] <= -1e37f) break;
        bool alive = (srem[i] == 0);
        if (alive && tid > i && srem[tid] == 0 && skey[tid] > -1e37f) {
            float4 A = sbox[i], B = sbox[tid];
            float lx = fmaxf(A.x, B.x), ly = fmaxf(A.y, B.y);
            float rx = fminf(A.z, B.z), ry = fminf(A.w, B.w);
            float w = fmaxf(__fsub_rn(rx, lx), 0.f);
            float h = fmaxf(__fsub_rn(ry, ly), 0.f);
            float inter = __fmul_rn(w, h);
            float denom = __fadd_rn(__fsub_rn(__fadd_rn(sarea[i], sarea[tid]), inter), 1e-9f);
            float iou = __fdiv_rn(inter, denom);
            if (iou > 0.7f) srem[tid] = 1;
        }
        __syncthreads();
    }

    if (skey[tid] > -1e37f && srem[tid] == 0 && sidx[tid] < cnt) {
        g_csc[base + sidx[tid]] = skey[tid];
    }
}

// ---------------- final: per-image stable sort, emit top-1000 -------------
__global__ void final_kernel(float* __restrict__ out) {
    __shared__ float skey[4096];
    __shared__ int sidx[4096];
    const int im = blockIdx.x;
    const int tid = threadIdx.x;

    for (int e = 0; e < 4; e++) {
        int i = tid + e * 1024;
        float v = -3.0f;
        if (i < DSEL) v = g_csc[im * DSEL + i];
        skey[i] = v;
        sidx[i] = i;
    }
    __syncthreads();

    for (int k = 2; k <= 4096; k <<= 1) {
        for (int j = k >> 1; j > 0; j >>= 1) {
            for (int e = 0; e < 4; e++) {
                int i = tid + e * 1024;
                int ixj = i ^ j;
                if (ixj > i) {
                    float ka = skey[i], kb = skey[ixj];
                    int ia = sidx[i], ib = sidx[ixj];
                    bool aGb = (ka > kb) || (ka == kb && ia < ib);
                    bool desc = ((i & k) == 0);
                    if (desc ? !aGb : aGb) {
                        skey[i] = kb; skey[ixj] = ka;
                        sidx[i] = ib; sidx[ixj] = ia;
                    }
                }
            }
            __syncthreads();
        }
    }

    if (tid < 1000) {
        float v = skey[tid];
        float* o = out + ((size_t)im * 1000 + tid) * 5;
        if (v > -0.5f) {
            float4 bx = g_cbox[im * DSEL + sidx[tid]];
            o[0] = bx.x; o[1] = bx.y; o[2] = bx.z; o[3] = bx.w; o[4] = v;
        } else {
            o[0] = 0.f; o[1] = 0.f; o[2] = 0.f; o[3] = 0.f; o[4] = 0.f;
        }
    }
}

// ---------------- launch ---------------------------------------------------
extern "C" void kernel_launch(void* const* d_in, const int* in_sizes, int n_in,
                              void* d_out, int out_size) {
    const float *fm[5] = {0, 0, 0, 0, 0}, *pr[5] = {0, 0, 0, 0, 0};
    const float *imsz = 0, *cw = 0, *cb = 0, *lw = 0, *lb = 0, *rw = 0, *rbv = 0;
    for (int i = 0; i < n_in; i++) {
        const float* p = (const float*)d_in[i];
        switch (in_sizes[i]) {
            case 7782400: fm[0] = p; break;
            case 1945600: fm[1] = p; break;
            case 486400:  fm[2] = p; break;
            case 126464:  fm[3] = p; break;
            case 35840:   fm[4] = p; break;
            case 182400:  pr[0] = p; break;
            case 45600:   pr[1] = p; break;
            case 11400:   pr[2] = p; break;
            case 2964:    pr[3] = p; break;
            case 840:     pr[4] = p; break;
            case 4:       imsz = p; break;
            case 589824:  cw = p; break;
            case 256:     cb = p; break;
            case 768:     lw = p; break;
            case 3:       lb = p; break;
            case 3072:    rw = p; break;
            case 12:      rbv = p; break;
            default: break;
        }
    }

    wtrans_kernel<<<576, 1024>>>(cw);
    conv_kernel<<<1456, 256>>>(fm[0], fm[1], fm[2], fm[3], fm[4], cb);
    head_kernel<<<dim3(635, 2), 256>>>(lw, lb, rw, rbv);
    topk_kernel<<<10, 1024>>>();
    sortsel_kernel<<<10, 1024>>>();
    maxinit_kernel<<<1, 1>>>();
    decode_kernel<<<(NTOT + 255) / 256, 256>>>(pr[0], pr[1], pr[2], pr[3], pr[4], imsz);
    nms_kernel<<<10, 1024>>>();
    final_kernel<<<2, 1024>>>((float*)d_out);
}

// round 10
// speedup vs baseline: 2.0770x; 1.1986x over previous
#include <cuda_runtime.h>
#include <math.h>
#include <float.h>

// ---------------- problem constants (fixed by setup_inputs) ----------------
#define DFULL 60801
#define DSEL  3951
#define NTOT  7902
#define LOG_MAXF 4.135166556742356f

__device__ const int d_HW[5]   = {15200, 3800, 950, 247, 70};
__device__ const int d_K[5]    = {1000, 1000, 1000, 741, 210};
__device__ const int d_AOFF[5] = {0, 45600, 57000, 59850, 60591};
__device__ const int d_COFF[5] = {0, 1000, 2000, 3000, 3741};

// conv merged-launch level decode tables
__device__ const int c_LB[5]   = {0, 1040, 1320, 1416, 1448};
__device__ const int c_NTX[5]  = {10, 5, 3, 2, 1};
__device__ const int c_NTY[5]  = {13, 7, 4, 2, 1};
__device__ const int c_H[5]    = {100, 50, 25, 13, 7};
__device__ const int c_W[5]    = {152, 76, 38, 19, 10};
__device__ const int c_HOFF[5] = {0, 7782400, 9728000, 10214400, 10340864};
// head merged-launch tables
__device__ const int h_HB[5]   = {0, 475, 594, 624, 632};

// ---------------- scratch (static device memory; no allocs) ----------------
__device__ float    g_h[10376704];
__device__ float    g_cwT[589824];        // weights transposed: [ic][tap][oc]
__device__ float    g_logit[2 * DFULL];
__device__ float    g_reg[2 * DFULL * 4];
__device__ int      g_topidx[10 * 1000];
__device__ float    g_toplog[10 * 1000];
__device__ float4   g_cbox[NTOT];
__device__ float    g_cscore[NTOT];
__device__ int      g_cvalid[NTOT];
__device__ float    g_csc[NTOT];
__device__ unsigned g_maxbits;

// ---------------- packed fp32x2 helpers (sm_103a FFMA2 path) --------------
typedef unsigned long long u64;

__device__ __forceinline__ u64 pack2(float lo, float hi) {
    u64 r;
    asm("mov.b64 %0, {%1, %2};" : "=l"(r) : "f"(lo), "f"(hi));
    return r;
}
__device__ __forceinline__ u64 fma2(u64 a, u64 b, u64 c) {
    u64 d;
    asm("fma.rn.f32x2 %0, %1, %2, %3;" : "=l"(d) : "l"(a), "l"(b), "l"(c));
    return d;
}
__device__ __forceinline__ void unpack2(float& lo, float& hi, u64 v) {
    asm("mov.b64 {%0, %1}, %2;" : "=f"(lo), "=f"(hi) : "l"(v));
}

// ---------------- cp.async helpers ----------------------------------------
__device__ __forceinline__ unsigned smem_u32(const void* p) {
    return (unsigned)__cvta_generic_to_shared(p);
}
__device__ __forceinline__ void cp4z(unsigned d, const void* s, int srcsz) {
    asm volatile("cp.async.ca.shared.global [%0], [%1], 4, %2;\n"
                 :: "r"(d), "l"(s), "r"(srcsz));
}
__device__ __forceinline__ void cp16(unsigned d, const void* s) {
    asm volatile("cp.async.cg.shared.global [%0], [%1], 16;\n"
                 :: "r"(d), "l"(s));
}
__device__ __forceinline__ void cp_commit() {
    asm volatile("cp.async.commit_group;\n");
}
template <int N>
__device__ __forceinline__ void cp_wait() {
    asm volatile("cp.async.wait_group %0;\n" :: "n"(N));
}

// ---------------- weight transpose: cw[oc][ic][tap] -> cwT[ic][tap][oc] ----
__global__ void wtrans_kernel(const float* __restrict__ cw) {
    int l = blockIdx.x * blockDim.x + threadIdx.x;
    if (l >= 589824) return;
    int oc = l & 255;
    int q = l >> 8;
    int tap = q % 9;
    int ic = q / 9;
    g_cwT[l] = cw[((size_t)oc * 256 + ic) * 9 + tap];
}

// ---------------- conv 3x3 (SAME) + bias + relu, ALL levels in one grid ---
// double-buffered cp.async pipeline; FFMA2 inner loop (oc-pairs)
// dynamic smem: ins 2x1600 floats + wsm 2x4608 floats = 49664 B
#define INS_F 1600
#define WSM_F 4608
__global__ __launch_bounds__(256, 2)
void conv_kernel(const float* __restrict__ f0, const float* __restrict__ f1,
                 const float* __restrict__ f2, const float* __restrict__ f3,
                 const float* __restrict__ f4,
                 const float* __restrict__ cb) {
    extern __shared__ float sm[];
    float* ins = sm;                  // [2][8*10*20]
    float* wsm = sm + 2 * INS_F;      // [2][8*9*64]

    const int b = blockIdx.x;
    const int lvl = (b < 1040) ? 0 : (b < 1320) ? 1 : (b < 1416) ? 2 : (b < 1448) ? 3 : 4;
    const int r = b - c_LB[lvl];
    const int ntx = c_NTX[lvl];
    const int nt = ntx * c_NTY[lvl];
    const int z = r / nt;
    const int rr = r % nt;
    const int ty = rr / ntx, tx = rr % ntx;
    const int img = z >> 2;
    const int ocBase = (z & 3) * 64;
    const int H = c_H[lvl], W = c_W[lvl];
    const int HWp = H * W;
    const int hoff = c_HOFF[lvl];
    const float* xin =
        ((lvl == 0) ? f0 : (lvl == 1) ? f1 : (lvl == 2) ? f2 : (lvl == 3) ? f3 : f4)
        + (size_t)img * 256 * HWp;

    const int tid = threadIdx.x;
    const int ocg = tid >> 5;          // 0..7 (uniform within warp)
    const int g = tid & 31;
    const int row = g >> 2;            // 0..7
    const int cg = g & 3;              // cols cg*4 .. cg*4+3
    const int x0 = tx * 16, y0 = ty * 8;

    // ---- precompute staging slots (once) ----
    // input: 1440 scalar elements, 6 per thread
    int s_plane[6];      // icj*HWp
    int s_off[6];        // gy*W+gx (0 if OOB)
    int s_sz[6];         // 4 = copy, 0 = zero-fill, -1 = no slot
    unsigned s_dst[6];   // smem addr in buffer 0
#pragma unroll
    for (int it = 0; it < 6; it++) {
        int l = tid + it * 256;
        if (l < 1440) {
            int icj = l / 180; int q = l % 180; int py = q / 18; int px = q % 18;
            int gy = y0 - 1 + py, gx = x0 - 1 + px;
            bool ok = (gy >= 0 && gy < H && gx >= 0 && gx < W);
            s_plane[it] = icj * HWp;
            s_off[it] = ok ? (gy * W + gx) : 0;
            s_sz[it] = ok ? 4 : 0;
            s_dst[it] = smem_u32(&ins[(icj * 10 + py) * 20 + px]);
        } else {
            s_sz[it] = -1; s_plane[it] = 0; s_off[it] = 0; s_dst[it] = 0;
        }
    }
    // weights: 1152 float4, 5 per thread (last partial)
    unsigned w_dst[5];
    int w_srcidx[5];     // float4 index within chunk slab; -1 = no slot
#pragma unroll
    for (int it = 0; it < 5; it++) {
        int l = tid + it * 256;
        if (l < 1152) {
            int pair = l >> 4, q = l & 15;
            w_dst[it] = smem_u32(&wsm[(pair << 6) + (q << 2)]);
            w_srcidx[it] = pair * 64 + q;
        } else {
            w_dst[it] = 0; w_srcidx[it] = -1;
        }
    }
    const float4* wb4 = ((const float4*)g_cwT) + (ocBase >> 2);

    // acc2[op][p]: oc-pair op, pixel p
    u64 acc2[4][4];
#pragma unroll
    for (int op = 0; op < 4; op++)
#pragma unroll
        for (int p = 0; p < 4; p++) acc2[op][p] = 0ull;

    // ---- stage chunk 0 into buffer 0 ----
    {
        const float* xx = xin;                 // ic0 = 0
#pragma unroll
        for (int it = 0; it < 6; it++)
            if (s_sz[it] >= 0) cp4z(s_dst[it], xx + s_plane[it] + s_off[it], s_sz[it]);
#pragma unroll
        for (int it = 0; it < 5; it++)
            if (w_srcidx[it] >= 0) cp16(w_dst[it], wb4 + w_srcidx[it]);
        cp_commit();
    }

    for (int c = 0; c < 32; c++) {
        const int cur = c & 1;
        if (c < 31) {
            const int nic0 = (c + 1) * 8;
            const unsigned ioff = (unsigned)((cur ^ 1) * INS_F * 4);
            const unsigned woff = (unsigned)((cur ^ 1) * WSM_F * 4);
            const float* xx = xin + nic0 * HWp;
            const float4* ws = wb4 + nic0 * 576;
#pragma unroll
            for (int it = 0; it < 6; it++)
                if (s_sz[it] >= 0) cp4z(s_dst[it] + ioff, xx + s_plane[it] + s_off[it], s_sz[it]);
#pragma unroll
            for (int it = 0; it < 5; it++)
                if (w_srcidx[it] >= 0) cp16(w_dst[it] + woff, ws + w_srcidx[it]);
            cp_commit();
            cp_wait<1>();
        } else {
            cp_wait<0>();
        }
        __syncthreads();

        const float* insb = ins + cur * INS_F;
        const float* wb = wsm + cur * WSM_F;

#pragma unroll 1
        for (int ic = 0; ic < 8; ic++) {
            const float* bp = &insb[(ic * 10 + row) * 20 + cg * 4];
#pragma unroll
            for (int ky = 0; ky < 3; ky++) {
                float4 v4 = *(const float4*)(bp + ky * 20);
                float2 v2 = *(const float2*)(bp + ky * 20 + 4);
                u64 r2[6];
                r2[0] = pack2(v4.x, v4.x); r2[1] = pack2(v4.y, v4.y);
                r2[2] = pack2(v4.z, v4.z); r2[3] = pack2(v4.w, v4.w);
                r2[4] = pack2(v2.x, v2.x); r2[5] = pack2(v2.y, v2.y);
#pragma unroll
                for (int kx = 0; kx < 3; kx++) {
                    const float* wp = &wb[(ic * 9 + ky * 3 + kx) * 64 + ocg * 8];
                    ulonglong2 wA = *(const ulonglong2*)wp;
                    ulonglong2 wB = *(const ulonglong2*)(wp + 4);
                    u64 wpair[4] = {wA.x, wA.y, wB.x, wB.y};
#pragma unroll
                    for (int op = 0; op < 4; op++)
#pragma unroll
                        for (int p = 0; p < 4; p++)
                            acc2[op][p] = fma2(wpair[op], r2[kx + p], acc2[op][p]);
                }
            }
        }
        if (c < 31) __syncthreads();   // compute done before next stage overwrites
    }

    // epilogue: unpack + bias + relu + store
    const int gy = y0 + row;
    if (gy < H) {
#pragma unroll
        for (int op = 0; op < 4; op++) {
            int oc0 = ocBase + ocg * 8 + op * 2;
            float b0 = cb[oc0], b1 = cb[oc0 + 1];
            float* dst0 = &g_h[hoff + ((size_t)img * 256 + oc0) * HWp + (size_t)gy * W];
            float* dst1 = dst0 + HWp;
#pragma unroll
            for (int p = 0; p < 4; p++) {
                int gx = x0 + cg * 4 + p;
                if (gx < W) {
                    float lo, hi;
                    unpack2(lo, hi, acc2[op][p]);
                    float v0 = lo + b0, v1 = hi + b1;
                    dst0[gx] = v0 > 0.f ? v0 : 0.f;
                    dst1[gx] = v1 > 0.f ? v1 : 0.f;
                }
            }
        }
    }
}

// ---------------- heads: 15 dot products per pixel, ALL levels one grid ---
__global__ void head_kernel(const float* __restrict__ lw, const float* __restrict__ lb,
                            const float* __restrict__ rw, const float* __restrict__ rb) {
    __shared__ float wsm[15 * 256];
    __shared__ float red[8][32][16];

    const int bx = blockIdx.x;
    const int lvl = (bx < 475) ? 0 : (bx < 594) ? 1 : (bx < 624) ? 2 : (bx < 632) ? 3 : 4;
    const int lb_blk = bx - h_HB[lvl];
    const int HW = d_HW[lvl];
    const int aoff = d_AOFF[lvl];
    const int hoff = c_HOFF[lvl];

    const int tid = threadIdx.x;
    for (int l = tid; l < 15 * 256; l += 256) {
        int o = l >> 8, c = l & 255;
        wsm[l] = (o < 3) ? lw[o * 256 + c] : rw[(o - 3) * 256 + c];
    }
    __syncthreads();

    const int img = blockIdx.y;
    const int pix = lb_blk * 32 + (tid & 31);
    const int cg = tid >> 5;

    float acc[15];
#pragma unroll
    for (int o = 0; o < 15; o++) acc[o] = 0.f;

    if (pix < HW) {
        const float* hp = g_h + hoff + ((size_t)img * 256 + cg * 32) * HW + pix;
#pragma unroll 4
        for (int j = 0; j < 32; j++) {
            float v = hp[(size_t)j * HW];
            int c = cg * 32 + j;
#pragma unroll
            for (int o = 0; o < 15; o++) acc[o] += v * wsm[o * 256 + c];
        }
    }
#pragma unroll
    for (int o = 0; o < 15; o++) red[cg][tid & 31][o] = acc[o];
    __syncthreads();

    for (int l = tid; l < 32 * 15; l += 256) {
        int px = l / 15, o = l % 15;
        float s = 0.f;
#pragma unroll
        for (int g = 0; g < 8; g++) s += red[g][px][o];
        int p = lb_blk * 32 + px;
        if (p < HW) {
            if (o < 3) {
                g_logit[(size_t)img * DFULL + aoff + p * 3 + o] = s + lb[o];
            } else {
                int rr = o - 3, a = rr >> 2, comp = rr & 3;
                g_reg[((size_t)img * DFULL + aoff + p * 3 + a) * 4 + comp] = s + rb[rr];
            }
        }
    }
}

// ---------------- exact top-k (set + lowest-index ties) radix select ------
__device__ __forceinline__ unsigned fkey(float f) {
    unsigned u = __float_as_uint(f);
    return (u & 0x80000000u) ? ~u : (u | 0x80000000u);
}

__global__ void topk_kernel() {
    const int b = blockIdx.x;
    const int im = b / 5, lvl = b % 5;
    const int L = 3 * d_HW[lvl];
    const int K = d_K[lvl];
    const float* src = g_logit + (size_t)im * DFULL + d_AOFF[lvl];
    int* oidx = g_topidx + b * 1000;
    float* olog = g_toplog + b * 1000;
    const int tid = threadIdx.x;
    const int nth = blockDim.x;

    if (L <= K) {
        for (int i = tid; i < L; i += nth) { oidx[i] = i; olog[i] = src[i]; }
        return;
    }

    __shared__ unsigned hist[2048];
    __shared__ unsigned sfxA[2048];
    __shared__ unsigned sfxB[2048];
    __shared__ int eqlist[1024];
    __shared__ int sh_d, sh_sub, sh_cnt, sh_eq;

    unsigned prefix = 0;
    int bitsdone = 0;
    int krem = K;
    const int widths[3] = {11, 11, 10};

    for (int pass = 0; pass < 3; pass++) {
        int wb = widths[pass];
        int nb = 1 << wb;
        int shift = 32 - bitsdone - wb;
        for (int l = tid; l < nb; l += nth) hist[l] = 0;
        __syncthreads();
        for (int i = tid; i < L; i += nth) {
            unsigned u = fkey(src[i]);
            if (bitsdone == 0 || (u >> (32 - bitsdone)) == prefix)
                atomicAdd(&hist[(u >> shift) & (nb - 1)], 1u);
        }
        __syncthreads();
        unsigned* s = sfxA; unsigned* d = sfxB;
        for (int l = tid; l < nb; l += nth) s[l] = hist[l];
        for (int off = 1; off < nb; off <<= 1) {
            __syncthreads();
            for (int l = tid; l < nb; l += nth)
                d[l] = s[l] + ((l + off < nb) ? s[l + off] : 0u);
            unsigned* t = s; s = d; d = t;
        }
        __syncthreads();
        for (int l = tid; l < nb; l += nth) {
            unsigned ge = s[l];
            unsigned gt = (l + 1 < nb) ? s[l + 1] : 0u;
            if ((int)ge >= krem && (int)gt < krem) { sh_d = l; sh_sub = (int)gt; }
        }
        __syncthreads();
        prefix = (prefix << wb) | (unsigned)sh_d;
        krem -= sh_sub;
        bitsdone += wb;
        __syncthreads();
    }

    const unsigned T = prefix;
    if (tid == 0) { sh_cnt = 0; sh_eq = 0; }
    __syncthreads();

    for (int i = tid; i < L; i += nth) {
        if (fkey(src[i]) == T) {
            int p = atomicAdd(&sh_eq, 1);
            if (p < 1024) eqlist[p] = i;
        }
    }
    __syncthreads();
    int m = sh_eq < 1024 ? sh_eq : 1024;
    for (int l = tid; l < 1024; l += nth)
        if (l >= m) eqlist[l] = 0x7FFFFFFF;
    __syncthreads();
    for (int k = 2; k <= 1024; k <<= 1) {
        for (int j = k >> 1; j > 0; j >>= 1) {
            if (tid < 1024) {
                int ixj = tid ^ j;
                if (ixj > tid) {
                    int a = eqlist[tid], bb = eqlist[ixj];
                    bool asc = ((tid & k) == 0);
                    if (asc ? (a > bb) : (a < bb)) { eqlist[tid] = bb; eqlist[ixj] = a; }
                }
            }
            __syncthreads();
        }
    }

    for (int i = tid; i < L; i += nth) {
        float f = src[i];
        if (fkey(f) > T) {
            int p = atomicAdd(&sh_cnt, 1);
            oidx[p] = i; olog[p] = f;
        }
    }
    __syncthreads();
    for (int l = tid; l < krem; l += nth) {
        int i = eqlist[l];
        int p = atomicAdd(&sh_cnt, 1);
        oidx[p] = i; olog[p] = src[i];
    }
}

// ---- sort each group's selection by (logit desc, index asc) --------------
__global__ void sortsel_kernel() {
    __shared__ float skey[1024];
    __shared__ int sidx[1024];
    const int b = blockIdx.x;
    const int K = d_K[b % 5];
    const int tid = threadIdx.x;

    float k = -FLT_MAX; int ix = 0x7FFFFFFF;
    if (tid < K) { k = g_toplog[b * 1000 + tid]; ix = g_topidx[b * 1000 + tid]; }
    skey[tid] = k; sidx[tid] = ix;
    __syncthreads();

    for (int kk = 2; kk <= 1024; kk <<= 1) {
        for (int j = kk >> 1; j > 0; j >>= 1) {
            int ixj = tid ^ j;
            if (ixj > tid) {
                float ka = skey[tid], kb = skey[ixj];
                int ia = sidx[tid], ib = sidx[ixj];
                bool aGb = (ka > kb) || (ka == kb && ia < ib);
                bool desc = ((tid & kk) == 0);
                if (desc ? !aGb : aGb) {
                    skey[tid] = kb; skey[ixj] = ka;
                    sidx[tid] = ib; sidx[ixj] = ia;
                }
            }
            __syncthreads();
        }
    }
    if (tid < K) { g_toplog[b * 1000 + tid] = skey[tid]; g_topidx[b * 1000 + tid] = sidx[tid]; }
}

// ---------------- decode + clip + validity + sigmoid + global max --------
__global__ void maxinit_kernel() { g_maxbits = 0u; }

__global__ void decode_kernel(const float* __restrict__ p0, const float* __restrict__ p1,
                              const float* __restrict__ p2, const float* __restrict__ p3,
                              const float* __restrict__ p4, const float* __restrict__ imsz) {
    int q = blockIdx.x * blockDim.x + threadIdx.x;
    if (q >= NTOT) return;
    int im = q / DSEL;
    int r = q % DSEL;
    int lvl = (r < 1000) ? 0 : (r < 2000) ? 1 : (r < 3000) ? 2 : (r < 3741) ? 3 : 4;
    int slot = r - d_COFF[lvl];
    int g = (im * 5 + lvl) * 1000 + slot;
    int idx = g_topidx[g];
    float logit = g_toplog[g];

    const float* pri =
        ((lvl == 0) ? p0 : (lvl == 1) ? p1 : (lvl == 2) ? p2 : (lvl == 3) ? p3 : p4) +
        (size_t)idx * 4;
    size_t rb = ((size_t)im * DFULL + d_AOFF[lvl] + idx) * 4;

    float dx = g_reg[rb + 0], dy = g_reg[rb + 1];
    float dw = fminf(g_reg[rb + 2], LOG_MAXF);
    float dh = fminf(g_reg[rb + 3], LOG_MAXF);
    float pcx = pri[0], pcy = pri[1], pw = pri[2], ph = pri[3];
    float cx = dx * pw + pcx, cy = dy * ph + pcy;
    float w = pw * expf(dw), h = ph * expf(dh);
    float x1 = cx - 0.5f * w, y1 = cy - 0.5f * h;
    float x2 = cx + 0.5f * w, y2 = cy + 0.5f * h;
    float Wc = imsz[im * 2 + 1], Hc = imsz[im * 2 + 0];
    x1 = fminf(fmaxf(x1, 0.f), Wc); x2 = fminf(fmaxf(x2, 0.f), Wc);
    y1 = fminf(fmaxf(y1, 0.f), Hc); y2 = fminf(fmaxf(y2, 0.f), Hc);

    g_cbox[q] = make_float4(x1, y1, x2, y2);
    g_cscore[q] = 1.f / (1.f + expf(-logit));
    g_cvalid[q] = ((x2 - x1) >= 0.001f) && ((y2 - y1) >= 0.001f);
    g_csc[q] = -1.0f;

    float m4 = fmaxf(fmaxf(x1, y1), fmaxf(x2, y2));
    atomicMax(&g_maxbits, __float_as_uint(m4));
}

// ---------------- per-group NMS: stable sort + bit-exact shifted IoU ------
__global__ void nms_kernel() {
    __shared__ float skey[1024];
    __shared__ int sidx[1024];
    __shared__ float4 sbox[1024];
    __shared__ float sarea[1024];
    __shared__ unsigned char srem[1024];

    const int b = blockIdx.x;
    const int im = b / 5, lvl = b % 5;
    const int base = im * DSEL + d_COFF[lvl];
    const int cnt = d_K[lvl];
    const int tid = threadIdx.x;

    float sc = -FLT_MAX;
    if (tid < cnt && g_cvalid[base + tid]) sc = g_cscore[base + tid];
    skey[tid] = sc;
    sidx[tid] = tid;

    for (int k = 2; k <= 1024; k <<= 1) {
        for (int j = k >> 1; j > 0; j >>= 1) {
            __syncthreads();
            int ixj = tid ^ j;
            if (ixj > tid) {
                float ka = skey[tid], kb = skey[ixj];
                int ia = sidx[tid], ib = sidx[ixj];
                bool aGb = (ka > kb) || (ka == kb && ia < ib);
                bool desc = ((tid & k) == 0);
                if (desc ? !aGb : aGb) {
                    skey[tid] = kb; skey[ixj] = ka;
                    sidx[tid] = ib; sidx[ixj] = ia;
                }
            }
        }
    }
    __syncthreads();

    {
        float M = __uint_as_float(g_maxbits);
        float off = __fmul_rn((float)(im * 10 + lvl), __fadd_rn(M, 1.0f));
        if (skey[tid] > -1e37f) {
            float4 bx = g_cbox[base + sidx[tid]];
            float sx1 = __fadd_rn(bx.x, off), sy1 = __fadd_rn(bx.y, off);
            float sx2 = __fadd_rn(bx.z, off), sy2 = __fadd_rn(bx.w, off);
            sbox[tid] = make_float4(sx1, sy1, sx2, sy2);
            sarea[tid] = __fmul_rn(__fsub_rn(sx2, sx1), __fsub_rn(sy2, sy1));
        } else {
            sbox[tid] = make_float4(0.f, 0.f, 0.f, 0.f);
            sarea[tid] = 0.f;
        }
        srem[tid] = 0;
    }
    __syncthreads();

    for (int i = 0; i < cnt; i++) {
        if (skey[i] <= -1e37f) break;
        bool alive = (srem[i] == 0);
        if (alive && tid > i && srem[tid] == 0 && skey[tid] > -1e37f) {
            float4 A = sbox[i], B = sbox[tid];
            float lx = fmaxf(A.x, B.x), ly = fmaxf(A.y, B.y);
            float rx = fminf(A.z, B.z), ry = fminf(A.w, B.w);
            float w = fmaxf(__fsub_rn(rx, lx), 0.f);
            float h = fmaxf(__fsub_rn(ry, ly), 0.f);
            float inter = __fmul_rn(w, h);
            float denom = __fadd_rn(__fsub_rn(__fadd_rn(sarea[i], sarea[tid]), inter), 1e-9f);
            float iou = __fdiv_rn(inter, denom);
            if (iou > 0.7f) srem[tid] = 1;
        }
        __syncthreads();
    }

    if (skey[tid] > -1e37f && srem[tid] == 0 && sidx[tid] < cnt) {
        g_csc[base + sidx[tid]] = skey[tid];
    }
}

// ---------------- final: per-image stable sort, emit top-1000 -------------
__global__ void final_kernel(float* __restrict__ out) {
    __shared__ float skey[4096];
    __shared__ int sidx[4096];
    const int im = blockIdx.x;
    const int tid = threadIdx.x;

    for (int e = 0; e < 4; e++) {
        int i = tid + e * 1024;
        float v = -3.0f;
        if (i < DSEL) v = g_csc[im * DSEL + i];
        skey[i] = v;
        sidx[i] = i;
    }
    __syncthreads();

    for (int k = 2; k <= 4096; k <<= 1) {
        for (int j = k >> 1; j > 0; j >>= 1) {
            for (int e = 0; e < 4; e++) {
                int i = tid + e * 1024;
                int ixj = i ^ j;
                if (ixj > i) {
                    float ka = skey[i], kb = skey[ixj];
                    int ia = sidx[i], ib = sidx[ixj];
                    bool aGb = (ka > kb) || (ka == kb && ia < ib);
                    bool desc = ((i & k) == 0);
                    if (desc ? !aGb : aGb) {
                        skey[i] = kb; skey[ixj] = ka;
                        sidx[i] = ib; sidx[ixj] = ia;
                    }
                }
            }
            __syncthreads();
        }
    }

    if (tid < 1000) {
        float v = skey[tid];
        float* o = out + ((size_t)im * 1000 + tid) * 5;
        if (v > -0.5f) {
            float4 bx = g_cbox[im * DSEL + sidx[tid]];
            o[0] = bx.x; o[1] = bx.y; o[2] = bx.z; o[3] = bx.w; o[4] = v;
        } else {
            o[0] = 0.f; o[1] = 0.f; o[2] = 0.f; o[3] = 0.f; o[4] = 0.f;
        }
    }
}

// ---------------- launch ---------------------------------------------------
extern "C" void kernel_launch(void* const* d_in, const int* in_sizes, int n_in,
                              void* d_out, int out_size) {
    const float *fm[5] = {0, 0, 0, 0, 0}, *pr[5] = {0, 0, 0, 0, 0};
    const float *imsz = 0, *cw = 0, *cb = 0, *lw = 0, *lb = 0, *rw = 0, *rbv = 0;
    for (int i = 0; i < n_in; i++) {
        const float* p = (const float*)d_in[i];
        switch (in_sizes[i]) {
            case 7782400: fm[0] = p; break;
            case 1945600: fm[1] = p; break;
            case 486400:  fm[2] = p; break;
            case 126464:  fm[3] = p; break;
            case 35840:   fm[4] = p; break;
            case 182400:  pr[0] = p; break;
            case 45600:   pr[1] = p; break;
            case 11400:   pr[2] = p; break;
            case 2964:    pr[3] = p; break;
            case 840:     pr[4] = p; break;
            case 4:       imsz = p; break;
            case 589824:  cw = p; break;
            case 256:     cb = p; break;
            case 768:     lw = p; break;
            case 3:       lb = p; break;
            case 3072:    rw = p; break;
            case 12:      rbv = p; break;
            default: break;
        }
    }

    const int conv_smem = (2 * INS_F + 2 * WSM_F) * 4;   // 49664 B
    cudaFuncSetAttribute(conv_kernel,
                         cudaFuncAttributeMaxDynamicSharedMemorySize, conv_smem);

    wtrans_kernel<<<576, 1024>>>(cw);
    conv_kernel<<<1456, 256, conv_smem>>>(fm[0], fm[1], fm[2], fm[3], fm[4], cb);
    head_kernel<<<dim3(635, 2), 256>>>(lw, lb, rw, rbv);
    topk_kernel<<<10, 1024>>>();
    sortsel_kernel<<<10, 1024>>>();
    maxinit_kernel<<<1, 1>>>();
    decode_kernel<<<(NTOT + 255) / 256, 256>>>(pr[0], pr[1], pr[2], pr[3], pr[4], imsz);
    nms_kernel<<<10, 1024>>>();
    final_kernel<<<2, 1024>>>((float*)d_out);
}